// round 4
// baseline (speedup 1.0000x reference)
#include <cuda_runtime.h>
#include <cuda_bf16.h>

#define W_ 768
#define H_ 768
#define N_ 16
#define HW_ (H_ * W_)
#define BX 32
#define BY 8
#define NT (BX * BY)           /* 256 */
#define R_ 8                   /* halo: covers |flow| < 8 */
#define TW (BX + 2 * R_ + 1)   /* 49 (odd stride -> good banks) */
#define TH (BY + 2 * R_ + 1)   /* 25 */
#define TSZ (TW * TH)          /* 1225 */
#define GX_ (W_ / BX)          /* 24  */
#define GY_ (H_ / BY)          /* 96  */
#define NBLK (GX_ * GY_ * N_)  /* 36864 */

__device__ float g_partials[NBLK];
__device__ unsigned long long g_ticket;  // monotonic across graph replays

// m1 = warp(GridXY, flo1) at integer pixel (ix,iy): closed form (GridXY linear).
__device__ __forceinline__ float2 m1_from(float fxv, float fyv, int ix, int iy)
{
    float gx = (float)ix + fxv;
    float gy = (float)iy + fyv;
    float x0f = floorf(gx), y0f = floorf(gy);
    float wx1 = gx - x0f, wy1 = gy - y0f;
    float wx0 = 1.0f - wx1, wy0 = 1.0f - wy1;
    int x0 = (int)x0f, y0 = (int)y0f;
    bool vx0 = ((unsigned)x0 < (unsigned)W_);
    bool vx1 = ((unsigned)(x0 + 1) < (unsigned)W_);
    bool vy0 = ((unsigned)y0 < (unsigned)H_);
    bool vy1 = ((unsigned)(y0 + 1) < (unsigned)H_);
    float c00 = (vx0 && vy0) ? wx0 * wy0 : 0.0f;
    float c10 = (vx1 && vy0) ? wx1 * wy0 : 0.0f;
    float c01 = (vx0 && vy1) ? wx0 * wy1 : 0.0f;
    float c11 = (vx1 && vy1) ? wx1 * wy1 : 0.0f;
    float m = (c00 + c10) + (c01 + c11);
    float cx1 = c10 + c11;   // weight on x0+1
    float cy1 = c01 + c11;   // weight on y0+1
    const float invW = 1.0f / (float)(W_ - 1);
    const float invH = 1.0f / (float)(H_ - 1);
    // ox = ((c00+c01)*x0 + (c10+c11)*(x0+1))*invW = (m*x0 + cx1)*invW
    float ox = fmaf(m, (float)x0, cx1) * invW;
    float oy = fmaf(m, (float)y0, cy1) * invH;
    float M = (m < 0.9999f) ? 0.0f : 1.0f;
    return make_float2(ox * M, oy * M);
}

// Tile gather: clamped (always-safe) LDS on the fast path, predicated rare
// global fallback only when the true local coord is outside the halo tile.
__device__ __forceinline__ float tload(const float* __restrict__ s,
                                       const float* __restrict__ g,
                                       int lx, int ly, int gidx)
{
    int sx = min(max(lx, 0), TW - 1);
    int sy = min(max(ly, 0), TH - 1);
    float v = s[sy * TW + sx];
    bool out = ((unsigned)lx >= (unsigned)TW) | ((unsigned)ly >= (unsigned)TH);
    if (out) v = __ldg(g + gidx);   // ~never taken (|flow| >= 8)
    return v;
}

// One direction: second warp (by f2own) of analytic m1(f1), f1 from smem tile.
__device__ __forceinline__ float dir_diff(const float* __restrict__ s1x,
                                          const float* __restrict__ s1y,
                                          const float* __restrict__ g1x,
                                          const float* __restrict__ g1y,
                                          float f2ox, float f2oy,
                                          int px, int py, int tx0, int ty0,
                                          float Gx, float Gy)
{
    float gx = (float)px + f2ox;
    float gy = (float)py + f2oy;
    float x0f = floorf(gx), y0f = floorf(gy);
    float wx1 = gx - x0f, wy1 = gy - y0f;
    float wx0 = 1.0f - wx1, wy0 = 1.0f - wy1;
    int x0 = (int)x0f, y0 = (int)y0f;
    int x1 = x0 + 1,   y1 = y0 + 1;
    bool vx0 = ((unsigned)x0 < (unsigned)W_);
    bool vx1 = ((unsigned)x1 < (unsigned)W_);
    bool vy0 = ((unsigned)y0 < (unsigned)H_);
    bool vy1 = ((unsigned)y1 < (unsigned)H_);
    int xc0 = min(max(x0, 0), W_ - 1);
    int xc1 = min(max(x1, 0), W_ - 1);
    int yc0 = min(max(y0, 0), H_ - 1);
    int yc1 = min(max(y1, 0), H_ - 1);
    int lx0 = xc0 - tx0, lx1 = xc1 - tx0;
    int ly0 = yc0 - ty0, ly1 = yc1 - ty0;
    int b00 = yc0 * W_ + xc0, b10 = yc0 * W_ + xc1;
    int b01 = yc1 * W_ + xc0, b11 = yc1 * W_ + xc1;

    float fx00 = tload(s1x, g1x, lx0, ly0, b00);
    float fx10 = tload(s1x, g1x, lx1, ly0, b10);
    float fx01 = tload(s1x, g1x, lx0, ly1, b01);
    float fx11 = tload(s1x, g1x, lx1, ly1, b11);
    float fy00 = tload(s1y, g1y, lx0, ly0, b00);
    float fy10 = tload(s1y, g1y, lx1, ly0, b10);
    float fy01 = tload(s1y, g1y, lx0, ly1, b01);
    float fy11 = tload(s1y, g1y, lx1, ly1, b11);

    float w00 = (vx0 && vy0) ? wx0 * wy0 : 0.0f;
    float w10 = (vx1 && vy0) ? wx1 * wy0 : 0.0f;
    float w01 = (vx0 && vy1) ? wx0 * wy1 : 0.0f;
    float w11 = (vx1 && vy1) ? wx1 * wy1 : 0.0f;

    float2 v00 = m1_from(fx00, fy00, x0, y0);
    float2 v10 = m1_from(fx10, fy10, x1, y0);
    float2 v01 = m1_from(fx01, fy01, x0, y1);
    float2 v11 = m1_from(fx11, fy11, x1, y1);

    float mask = (w00 + w10) + (w01 + w11);
    float mx = fmaf(w00, v00.x, fmaf(w10, v10.x, fmaf(w01, v01.x, w11 * v11.x)));
    float my = fmaf(w00, v00.y, fmaf(w10, v10.y, fmaf(w01, v01.y, w11 * v11.y)));

    float M = (mask < 0.9999f) ? 0.0f : 1.0f;
    mx *= M; my *= M;
    float dx = Gx - mx, dy = Gy - my;
    return sqrtf(fmaf(dx, dx, fmaf(dy, dy, 1.0e-6f)));  // EPS^2
}

__global__ __launch_bounds__(NT)
void fused_cycle_kernel(const float* __restrict__ A, const float* __restrict__ B,
                        float* __restrict__ out)
{
    __shared__ float sAx[TSZ], sAy[TSZ], sBx[TSZ], sBy[TSZ];

    int n = blockIdx.z;
    const float* Ax = A + (size_t)n * 2 * HW_;
    const float* Ay = Ax + HW_;
    const float* Bx = B + (size_t)n * 2 * HW_;
    const float* By = Bx + HW_;

    int tx0 = blockIdx.x * BX - R_;
    int ty0 = blockIdx.y * BY - R_;
    int tid = threadIdx.y * BX + threadIdx.x;

    // Coalesced cooperative fill; coords clamped (out-of-image cells are only
    // ever read with zero weight, value irrelevant but must be finite).
    #pragma unroll
    for (int i = tid; i < TSZ; i += NT) {
        int ly = i / TW, lx = i - ly * TW;
        int gx = min(max(tx0 + lx, 0), W_ - 1);
        int gy = min(max(ty0 + ly, 0), H_ - 1);
        int idx = gy * W_ + gx;
        sAx[i] = __ldg(Ax + idx);
        sAy[i] = __ldg(Ay + idx);
        sBx[i] = __ldg(Bx + idx);
        sBy[i] = __ldg(By + idx);
    }
    __syncthreads();

    int px = blockIdx.x * BX + threadIdx.x;
    int py = blockIdx.y * BY + threadIdx.y;
    const float invW = 1.0f / (float)(W_ - 1);
    const float invH = 1.0f / (float)(H_ - 1);
    float Gx = (float)px * invW;
    float Gy = (float)py * invH;

    int lown = (threadIdx.y + R_) * TW + (threadIdx.x + R_);
    float aox = sAx[lown], aoy = sAy[lown];
    float box = sBx[lown], boy = sBy[lown];

    // ABA: gather A at corners of p+B(p).  BAB: gather B at corners of p+A(p).
    float s = dir_diff(sAx, sAy, Ax, Ay, box, boy, px, py, tx0, ty0, Gx, Gy)
            + dir_diff(sBx, sBy, Bx, By, aox, aoy, px, py, tx0, ty0, Gx, Gy);

    // Block reduction (8 warps)
    #pragma unroll
    for (int o = 16; o > 0; o >>= 1)
        s += __shfl_down_sync(0xffffffffu, s, o);
    __shared__ float shred[NT / 32];
    if ((tid & 31) == 0) shred[tid >> 5] = s;
    __syncthreads();
    if (tid < 8) {
        float v = shred[tid];
        #pragma unroll
        for (int o = 4; o > 0; o >>= 1)
            v += __shfl_down_sync(0x000000ffu, v, o);
        if (tid == 0) {
            int bid = blockIdx.x + GX_ * (blockIdx.y + GY_ * blockIdx.z);
            g_partials[bid] = v;
        }
    }

    // Last-block-standing final reduce (fused; deterministic).
    __shared__ bool amLast;
    __threadfence();
    if (tid == 0) {
        unsigned long long old = atomicAdd(&g_ticket, 1ULL);
        amLast = ((old % (unsigned long long)NBLK) == (unsigned long long)(NBLK - 1));
    }
    __syncthreads();
    if (amLast) {
        const float4* p4 = (const float4*)g_partials;  // NBLK % 4 == 0
        const int n4 = NBLK / 4;                       // 9216
        double acc = 0.0;
        for (int i = tid; i < n4; i += NT) {
            float4 v = __ldcg(p4 + i);
            acc += (double)((v.x + v.y) + (v.z + v.w));
        }
        #pragma unroll
        for (int o = 16; o > 0; o >>= 1)
            acc += __shfl_down_sync(0xffffffffu, acc, o);
        __shared__ double shd[NT / 32];
        if ((tid & 31) == 0) shd[tid >> 5] = acc;
        __syncthreads();
        if (tid < 8) {
            double v = shd[tid];
            #pragma unroll
            for (int o = 4; o > 0; o >>= 1)
                v += __shfl_down_sync(0x000000ffu, v, o);
            if (tid == 0)
                out[0] = (float)(v / ((double)N_ * (double)HW_));
        }
    }
}

extern "C" void kernel_launch(void* const* d_in, const int* in_sizes, int n_in,
                              void* d_out, int out_size)
{
    const float* A = (const float*)d_in[0];  // UV_AtoB
    const float* B = (const float*)d_in[1];  // UV_BtoA
    dim3 block(BX, BY);
    dim3 grid(GX_, GY_, N_);
    fused_cycle_kernel<<<grid, block>>>(A, B, (float*)d_out);
}

// round 5
// speedup vs baseline: 1.3285x; 1.3285x over previous
#include <cuda_runtime.h>
#include <cuda_bf16.h>

#define W_ 768
#define H_ 768
#define N_ 16
#define HW_ (H_ * W_)
#define BX 32
#define BY 16
#define NT (BX * BY)           /* 512 */
#define R_ 8                   /* halo: covers |flow| < 8 */
#define TW (BX + 2 * R_ + 1)   /* 49 */
#define TH (BY + 2 * R_ + 1)   /* 33 */
#define TSZ (TW * TH)          /* 1617 */
#define GX_ (W_ / BX)          /* 24 */
#define GY_ (H_ / BY)          /* 48 */
#define NBLK (GX_ * GY_ * N_)  /* 18432 */
#define EPS2 1.0e-6f
#define INVW (1.0f / 767.0f)
#define INVH (1.0f / 767.0f)
#define WM1F 767.0f
#define HM1F 767.0f

__device__ float g_partials[NBLK];
__device__ unsigned long long g_ticket;  // monotonic across graph replays

// General m1 = warp(GridXY, flo1) at integer pixel (ix,iy): closed form.
__device__ __forceinline__ float2 m1_from(float fxv, float fyv, int ix, int iy)
{
    float gx = (float)ix + fxv;
    float gy = (float)iy + fyv;
    float x0f = floorf(gx), y0f = floorf(gy);
    float wx1 = gx - x0f, wy1 = gy - y0f;
    float wx0 = 1.0f - wx1, wy0 = 1.0f - wy1;
    int x0 = (int)x0f, y0 = (int)y0f;
    bool vx0 = ((unsigned)x0 < (unsigned)W_);
    bool vx1 = ((unsigned)(x0 + 1) < (unsigned)W_);
    bool vy0 = ((unsigned)y0 < (unsigned)H_);
    bool vy1 = ((unsigned)(y0 + 1) < (unsigned)H_);
    float c00 = (vx0 && vy0) ? wx0 * wy0 : 0.0f;
    float c10 = (vx1 && vy0) ? wx1 * wy0 : 0.0f;
    float c01 = (vx0 && vy1) ? wx0 * wy1 : 0.0f;
    float c11 = (vx1 && vy1) ? wx1 * wy1 : 0.0f;
    float m = (c00 + c10) + (c01 + c11);
    float cx1 = c10 + c11;
    float cy1 = c01 + c11;
    float ox = fmaf(m, (float)x0, cx1) * INVW;
    float oy = fmaf(m, (float)y0, cy1) * INVH;
    float M = (m < 0.9999f) ? 0.0f : 1.0f;
    return make_float2(ox * M, oy * M);
}

// General (boundary) path given the 8 corner flow values.
__device__ __forceinline__ float slow_eval(
    float fx00, float fx10, float fx01, float fx11,
    float fy00, float fy10, float fy01, float fy11,
    int x0, int y0, float wx0, float wx1, float wy0, float wy1,
    float Gx, float Gy)
{
    int x1 = x0 + 1, y1 = y0 + 1;
    bool vx0 = ((unsigned)x0 < (unsigned)W_);
    bool vx1 = ((unsigned)x1 < (unsigned)W_);
    bool vy0 = ((unsigned)y0 < (unsigned)H_);
    bool vy1 = ((unsigned)y1 < (unsigned)H_);
    float w00 = (vx0 && vy0) ? wx0 * wy0 : 0.0f;
    float w10 = (vx1 && vy0) ? wx1 * wy0 : 0.0f;
    float w01 = (vx0 && vy1) ? wx0 * wy1 : 0.0f;
    float w11 = (vx1 && vy1) ? wx1 * wy1 : 0.0f;

    float2 v00 = m1_from(fx00, fy00, x0, y0);
    float2 v10 = m1_from(fx10, fy10, x1, y0);
    float2 v01 = m1_from(fx01, fy01, x0, y1);
    float2 v11 = m1_from(fx11, fy11, x1, y1);

    float mask = (w00 + w10) + (w01 + w11);
    float mx = fmaf(w00, v00.x, fmaf(w10, v10.x, fmaf(w01, v01.x, w11 * v11.x)));
    float my = fmaf(w00, v00.y, fmaf(w10, v10.y, fmaf(w01, v01.y, w11 * v11.y)));
    float M = (mask < 0.9999f) ? 0.0f : 1.0f;
    mx *= M; my *= M;
    float dx = Gx - mx, dy = Gy - my;
    return sqrtf(fmaf(dx, dx, fmaf(dy, dy, EPS2)));
}

// One direction: second warp (by f2own) of analytic m1(f1).
// Tile content == clamped-global semantics (fill is coordinate-clamped), so
// unclamped local corner indices are valid for BOTH interior and boundary
// paths whenever |f2| < ~8 (tile guard). Fast path: full telescoped identity.
__device__ __forceinline__ float dir_diff(const float* __restrict__ s1x,
                                          const float* __restrict__ s1y,
                                          const float* __restrict__ g1x,
                                          const float* __restrict__ g1y,
                                          float f2x, float f2y,
                                          int px, int py, int tx0, int ty0,
                                          float Gx, float Gy)
{
    float sxf = (float)px + f2x;
    float syf = (float)py + f2y;
    float x0f = floorf(sxf), y0f = floorf(syf);
    float wx1 = sxf - x0f, wy1 = syf - y0f;
    float wx0 = 1.0f - wx1, wy0 = 1.0f - wy1;
    int x0 = (int)x0f, y0 = (int)y0f;
    int lx0 = x0 - tx0, ly0 = y0 - ty0;

    float fx00, fx10, fx01, fx11, fy00, fy10, fy01, fy11;

    if (((unsigned)lx0 <= (unsigned)(TW - 2)) &
        ((unsigned)ly0 <= (unsigned)(TH - 2))) {
        int b = ly0 * TW + lx0;
        fx00 = s1x[b];          fx10 = s1x[b + 1];
        fx01 = s1x[b + TW];     fx11 = s1x[b + TW + 1];
        fy00 = s1y[b];          fy10 = s1y[b + 1];
        fy01 = s1y[b + TW];     fy11 = s1y[b + TW + 1];

        // Interior test: outer sample in-image AND (conservatively) every
        // corner's m1 sample in-image.
        float x1f = x0f + 1.0f, y1f = y0f + 1.0f;
        float mnfx = fminf(fminf(fx00, fx01), fminf(fx10, fx11));
        float mxfx = fmaxf(fmaxf(fx00, fx01), fmaxf(fx10, fx11));
        float mnfy = fminf(fminf(fy00, fy01), fminf(fy10, fy11));
        float mxfy = fmaxf(fmaxf(fy00, fy01), fmaxf(fy10, fy11));
        bool inner = (sxf >= 0.0f) & (sxf <= WM1F) &
                     (syf >= 0.0f) & (syf <= HM1F) &
                     (x0f + mnfx >= 0.0f) & (x1f + mxfx <= WM1F) &
                     (y0f + mnfy >= 0.0f) & (y1f + mxfy <= HM1F);
        if (inner) {
            // Telescoped interior formula:
            // diff_x = (f2x + bilerp(f1x)) * invW (sign irrelevant, squared)
            float ftx = fmaf(wx1, fx10 - fx00, fx00);
            float fbx = fmaf(wx1, fx11 - fx01, fx01);
            float bfx = fmaf(wy1, fbx - ftx, ftx);
            float fty = fmaf(wx1, fy10 - fy00, fy00);
            float fby = fmaf(wx1, fy11 - fy01, fy01);
            float bfy = fmaf(wy1, fby - fty, fty);
            float dx = (f2x + bfx) * INVW;
            float dy = (f2y + bfy) * INVH;
            return sqrtf(fmaf(dx, dx, fmaf(dy, dy, EPS2)));
        }
        // boundary band: general math on already-loaded tile values
    } else {
        // |f2| >= ~8: essentially never. Full clamped-global path.
        int x1 = x0 + 1, y1 = y0 + 1;
        int xc0 = min(max(x0, 0), W_ - 1);
        int xc1 = min(max(x1, 0), W_ - 1);
        int yc0 = min(max(y0, 0), H_ - 1);
        int yc1 = min(max(y1, 0), H_ - 1);
        int b00 = yc0 * W_ + xc0, b10 = yc0 * W_ + xc1;
        int b01 = yc1 * W_ + xc0, b11 = yc1 * W_ + xc1;
        fx00 = __ldg(g1x + b00); fx10 = __ldg(g1x + b10);
        fx01 = __ldg(g1x + b01); fx11 = __ldg(g1x + b11);
        fy00 = __ldg(g1y + b00); fy10 = __ldg(g1y + b10);
        fy01 = __ldg(g1y + b01); fy11 = __ldg(g1y + b11);
    }
    return slow_eval(fx00, fx10, fx01, fx11, fy00, fy10, fy01, fy11,
                     x0, y0, wx0, wx1, wy0, wy1, Gx, Gy);
}

__global__ __launch_bounds__(NT)
void fused_cycle_kernel(const float* __restrict__ A, const float* __restrict__ B,
                        float* __restrict__ out)
{
    __shared__ float sAx[TSZ], sAy[TSZ], sBx[TSZ], sBy[TSZ];

    int n = blockIdx.z;
    const float* Ax = A + (size_t)n * 2 * HW_;
    const float* Ay = Ax + HW_;
    const float* Bx = B + (size_t)n * 2 * HW_;
    const float* By = Bx + HW_;

    int tx0 = blockIdx.x * BX - R_;
    int ty0 = blockIdx.y * BY - R_;
    int tid = threadIdx.y * BX + threadIdx.x;

    // Coordinate-clamped cooperative fill: tile cell == clamped-global value.
    #pragma unroll
    for (int i = tid; i < TSZ; i += NT) {
        int ly = i / TW, lx = i - ly * TW;
        int gx = min(max(tx0 + lx, 0), W_ - 1);
        int gy = min(max(ty0 + ly, 0), H_ - 1);
        int idx = gy * W_ + gx;
        sAx[i] = __ldg(Ax + idx);
        sAy[i] = __ldg(Ay + idx);
        sBx[i] = __ldg(Bx + idx);
        sBy[i] = __ldg(By + idx);
    }
    __syncthreads();

    int px = blockIdx.x * BX + threadIdx.x;
    int py = blockIdx.y * BY + threadIdx.y;
    float Gx = (float)px * INVW;
    float Gy = (float)py * INVH;

    int lown = (threadIdx.y + R_) * TW + (threadIdx.x + R_);
    float aox = sAx[lown], aoy = sAy[lown];
    float box = sBx[lown], boy = sBy[lown];

    // ABA: gather A at corners of p+B(p).  BAB: gather B at corners of p+A(p).
    float s = dir_diff(sAx, sAy, Ax, Ay, box, boy, px, py, tx0, ty0, Gx, Gy)
            + dir_diff(sBx, sBy, Bx, By, aox, aoy, px, py, tx0, ty0, Gx, Gy);

    // Block reduction (16 warps)
    #pragma unroll
    for (int o = 16; o > 0; o >>= 1)
        s += __shfl_down_sync(0xffffffffu, s, o);
    __shared__ float shred[NT / 32];
    if ((tid & 31) == 0) shred[tid >> 5] = s;
    __syncthreads();
    if (tid < 16) {
        float v = shred[tid];
        #pragma unroll
        for (int o = 8; o > 0; o >>= 1)
            v += __shfl_down_sync(0x0000ffffu, v, o);
        if (tid == 0) {
            int bid = blockIdx.x + GX_ * (blockIdx.y + GY_ * blockIdx.z);
            g_partials[bid] = v;
        }
    }

    // Last-block-standing fused final reduce (deterministic).
    __shared__ bool amLast;
    __threadfence();
    if (tid == 0) {
        unsigned long long old = atomicAdd(&g_ticket, 1ULL);
        amLast = ((old % (unsigned long long)NBLK) == (unsigned long long)(NBLK - 1));
    }
    __syncthreads();
    if (amLast) {
        const float4* p4 = (const float4*)g_partials;  // NBLK % 4 == 0
        const int n4 = NBLK / 4;                       // 4608
        double acc = 0.0;
        for (int i = tid; i < n4; i += NT) {
            float4 v = __ldcg(p4 + i);
            acc += (double)((v.x + v.y) + (v.z + v.w));
        }
        #pragma unroll
        for (int o = 16; o > 0; o >>= 1)
            acc += __shfl_down_sync(0xffffffffu, acc, o);
        __shared__ double shd[NT / 32];
        if ((tid & 31) == 0) shd[tid >> 5] = acc;
        __syncthreads();
        if (tid < 16) {
            double v = shd[tid];
            #pragma unroll
            for (int o = 8; o > 0; o >>= 1)
                v += __shfl_down_sync(0x0000ffffu, v, o);
            if (tid == 0)
                out[0] = (float)(v / ((double)N_ * (double)HW_));
        }
    }
}

extern "C" void kernel_launch(void* const* d_in, const int* in_sizes, int n_in,
                              void* d_out, int out_size)
{
    const float* A = (const float*)d_in[0];  // UV_AtoB
    const float* B = (const float*)d_in[1];  // UV_BtoA
    dim3 block(BX, BY);
    dim3 grid(GX_, GY_, N_);
    fused_cycle_kernel<<<grid, block>>>(A, B, (float*)d_out);
}

// round 6
// speedup vs baseline: 1.5895x; 1.1964x over previous
#include <cuda_runtime.h>
#include <cuda_bf16.h>

#define W_ 768
#define H_ 768
#define N_ 16
#define HW_ (H_ * W_)
#define BX 32
#define BY 16
#define NT (BX * BY)           /* 512 */
#define R_ 8                   /* halo: covers |flow| < 8 */
#define TW 52                  /* padded tile width (mult of 4), data cols 0..51 */
#define TH (BY + 2 * R_ + 1)   /* 33 */
#define TSZ (TW * TH)          /* 1716 float2 cells */
#define NV4 (TSZ / 4)          /* 429 float4-groups per plane */
#define GX_ (W_ / BX)          /* 24 */
#define GY_ (H_ / BY)          /* 48 */
#define NBLK (GX_ * GY_ * N_)  /* 18432 */
#define EPS2 1.0e-6f
#define INVW (1.0f / 767.0f)
#define INVH (1.0f / 767.0f)
#define WM1F 767.0f
#define HM1F 767.0f

__device__ float g_partials[NBLK];
__device__ unsigned long long g_ticket;  // monotonic across graph replays

// General m1 = warp(GridXY, flo1) at integer pixel (ix,iy): closed form.
__device__ __forceinline__ float2 m1_from(float fxv, float fyv, int ix, int iy)
{
    float gx = (float)ix + fxv;
    float gy = (float)iy + fyv;
    float x0f = floorf(gx), y0f = floorf(gy);
    float wx1 = gx - x0f, wy1 = gy - y0f;
    float wx0 = 1.0f - wx1, wy0 = 1.0f - wy1;
    int x0 = (int)x0f, y0 = (int)y0f;
    bool vx0 = ((unsigned)x0 < (unsigned)W_);
    bool vx1 = ((unsigned)(x0 + 1) < (unsigned)W_);
    bool vy0 = ((unsigned)y0 < (unsigned)H_);
    bool vy1 = ((unsigned)(y0 + 1) < (unsigned)H_);
    float c00 = (vx0 && vy0) ? wx0 * wy0 : 0.0f;
    float c10 = (vx1 && vy0) ? wx1 * wy0 : 0.0f;
    float c01 = (vx0 && vy1) ? wx0 * wy1 : 0.0f;
    float c11 = (vx1 && vy1) ? wx1 * wy1 : 0.0f;
    float m = (c00 + c10) + (c01 + c11);
    float cx1 = c10 + c11;
    float cy1 = c01 + c11;
    float ox = fmaf(m, (float)x0, cx1) * INVW;
    float oy = fmaf(m, (float)y0, cy1) * INVH;
    float M = (m < 0.9999f) ? 0.0f : 1.0f;
    return make_float2(ox * M, oy * M);
}

// General (boundary) path given the 4 corner flow float2s.
__device__ __forceinline__ float slow_eval(
    float2 f00, float2 f10, float2 f01, float2 f11,
    int x0, int y0, float wx0, float wx1, float wy0, float wy1,
    float Gx, float Gy)
{
    int x1 = x0 + 1, y1 = y0 + 1;
    bool vx0 = ((unsigned)x0 < (unsigned)W_);
    bool vx1 = ((unsigned)x1 < (unsigned)W_);
    bool vy0 = ((unsigned)y0 < (unsigned)H_);
    bool vy1 = ((unsigned)y1 < (unsigned)H_);
    float w00 = (vx0 && vy0) ? wx0 * wy0 : 0.0f;
    float w10 = (vx1 && vy0) ? wx1 * wy0 : 0.0f;
    float w01 = (vx0 && vy1) ? wx0 * wy1 : 0.0f;
    float w11 = (vx1 && vy1) ? wx1 * wy1 : 0.0f;

    float2 v00 = m1_from(f00.x, f00.y, x0, y0);
    float2 v10 = m1_from(f10.x, f10.y, x1, y0);
    float2 v01 = m1_from(f01.x, f01.y, x0, y1);
    float2 v11 = m1_from(f11.x, f11.y, x1, y1);

    float mask = (w00 + w10) + (w01 + w11);
    float mx = fmaf(w00, v00.x, fmaf(w10, v10.x, fmaf(w01, v01.x, w11 * v11.x)));
    float my = fmaf(w00, v00.y, fmaf(w10, v10.y, fmaf(w01, v01.y, w11 * v11.y)));
    float M = (mask < 0.9999f) ? 0.0f : 1.0f;
    mx *= M; my *= M;
    float dx = Gx - mx, dy = Gy - my;
    return sqrtf(fmaf(dx, dx, fmaf(dy, dy, EPS2)));
}

// One direction: second warp (by f2own) of analytic m1(f1), f1 from AoS tile.
__device__ __forceinline__ float dir_diff(const float2* __restrict__ t1,
                                          const float* __restrict__ g1x,
                                          const float* __restrict__ g1y,
                                          float f2x, float f2y,
                                          int px, int py, int tx0, int ty0,
                                          float Gx, float Gy)
{
    float sxf = (float)px + f2x;
    float syf = (float)py + f2y;
    float x0f = floorf(sxf), y0f = floorf(syf);
    float wx1 = sxf - x0f, wy1 = syf - y0f;
    float wx0 = 1.0f - wx1, wy0 = 1.0f - wy1;
    int x0 = (int)x0f, y0 = (int)y0f;

    int lx0 = x0 - tx0, ly0 = y0 - ty0;
    if (((unsigned)lx0 <= (unsigned)(TW - 2)) &
        ((unsigned)ly0 <= (unsigned)(TH - 2))) {
        int b = ly0 * TW + lx0;
        float2 f00 = t1[b];
        float2 f10 = t1[b + 1];
        float2 f01 = t1[b + TW];
        float2 f11 = t1[b + TW + 1];

        // Conservative interior test: outer sample in-image AND all corner
        // m1 samples in-image -> every weight/mask is 1 -> telescoped form.
        float x1f = x0f + 1.0f, y1f = y0f + 1.0f;
        float mnfx = fminf(fminf(f00.x, f01.x), fminf(f10.x, f11.x));
        float mxfx = fmaxf(fmaxf(f00.x, f01.x), fmaxf(f10.x, f11.x));
        float mnfy = fminf(fminf(f00.y, f01.y), fminf(f10.y, f11.y));
        float mxfy = fmaxf(fmaxf(f00.y, f01.y), fmaxf(f10.y, f11.y));
        bool inner = (sxf >= 0.0f) & (sxf <= WM1F) &
                     (syf >= 0.0f) & (syf <= HM1F) &
                     (x0f + mnfx >= 0.0f) & (x1f + mxfx <= WM1F) &
                     (y0f + mnfy >= 0.0f) & (y1f + mxfy <= HM1F);
        if (inner) {
            float ftx = fmaf(wx1, f10.x - f00.x, f00.x);
            float fbx = fmaf(wx1, f11.x - f01.x, f01.x);
            float bfx = fmaf(wy1, fbx - ftx, ftx);
            float fty = fmaf(wx1, f10.y - f00.y, f00.y);
            float fby = fmaf(wx1, f11.y - f01.y, f01.y);
            float bfy = fmaf(wy1, fby - fty, fty);
            float dx = (f2x + bfx) * INVW;
            float dy = (f2y + bfy) * INVH;
            return sqrtf(fmaf(dx, dx, fmaf(dy, dy, EPS2)));
        }
        return slow_eval(f00, f10, f01, f11, x0, y0, wx0, wx1, wy0, wy1, Gx, Gy);
    }
    // |f2| >= ~8: essentially never. Full clamped-global path.
    {
        int x1 = x0 + 1, y1 = y0 + 1;
        int xc0 = min(max(x0, 0), W_ - 1);
        int xc1 = min(max(x1, 0), W_ - 1);
        int yc0 = min(max(y0, 0), H_ - 1);
        int yc1 = min(max(y1, 0), H_ - 1);
        int b00 = yc0 * W_ + xc0, b10 = yc0 * W_ + xc1;
        int b01 = yc1 * W_ + xc0, b11 = yc1 * W_ + xc1;
        float2 f00 = make_float2(__ldg(g1x + b00), __ldg(g1y + b00));
        float2 f10 = make_float2(__ldg(g1x + b10), __ldg(g1y + b10));
        float2 f01 = make_float2(__ldg(g1x + b01), __ldg(g1y + b01));
        float2 f11 = make_float2(__ldg(g1x + b11), __ldg(g1y + b11));
        return slow_eval(f00, f10, f01, f11, x0, y0, wx0, wx1, wy0, wy1, Gx, Gy);
    }
}

__global__ __launch_bounds__(NT)
void fused_cycle_kernel(const float* __restrict__ A, const float* __restrict__ B,
                        float* __restrict__ out)
{
    __shared__ float2 tA[TSZ];
    __shared__ float2 tB[TSZ];

    int n = blockIdx.z;
    const float* Ax = A + (size_t)n * 2 * HW_;
    const float* Ay = Ax + HW_;
    const float* Bx = B + (size_t)n * 2 * HW_;
    const float* By = Bx + HW_;

    int tx0 = blockIdx.x * BX - R_;
    int ty0 = blockIdx.y * BY - R_;
    int tid = threadIdx.y * BX + threadIdx.x;

    // Tile fill: tile cell == clamped-global value.
    if (blockIdx.x >= 1 && blockIdx.x <= GX_ - 2) {
        // x-interior: rows [tx0, tx0+52) fully in-image, tx0 % 4 == 0
        // -> float4 global loads, float4 smem stores (tile cells 16B aligned).
        if (tid < NV4) {
            int i = tid;                 // NV4 = 429 < NT, single pass
            int ly = i / (TW / 4);
            int lxg = (i - ly * (TW / 4)) * 4;
            int gy = min(max(ty0 + ly, 0), H_ - 1);
            int idx = gy * W_ + tx0 + lxg;
            float4 ax = *(const float4*)(Ax + idx);
            float4 ay = *(const float4*)(Ay + idx);
            float4 bx = *(const float4*)(Bx + idx);
            float4 by = *(const float4*)(By + idx);
            int c = ly * TW + lxg;
            *(float4*)&tA[c]     = make_float4(ax.x, ay.x, ax.y, ay.y);
            *(float4*)&tA[c + 2] = make_float4(ax.z, ay.z, ax.w, ay.w);
            *(float4*)&tB[c]     = make_float4(bx.x, by.x, bx.y, by.y);
            *(float4*)&tB[c + 2] = make_float4(bx.z, by.z, bx.w, by.w);
        }
    } else {
        // x-edge blocks: scalar clamped fill.
        for (int i = tid; i < TSZ; i += NT) {
            int ly = i / TW, lx = i - ly * TW;
            int gx = min(max(tx0 + lx, 0), W_ - 1);
            int gy = min(max(ty0 + ly, 0), H_ - 1);
            int idx = gy * W_ + gx;
            tA[i] = make_float2(__ldg(Ax + idx), __ldg(Ay + idx));
            tB[i] = make_float2(__ldg(Bx + idx), __ldg(By + idx));
        }
    }
    __syncthreads();

    int px = blockIdx.x * BX + threadIdx.x;
    int py = blockIdx.y * BY + threadIdx.y;
    float Gx = (float)px * INVW;
    float Gy = (float)py * INVH;

    int lown = (threadIdx.y + R_) * TW + (threadIdx.x + R_);
    float2 ao = tA[lown];
    float2 bo = tB[lown];

    // ABA: gather A at corners of p+B(p).  BAB: gather B at corners of p+A(p).
    float s = dir_diff(tA, Ax, Ay, bo.x, bo.y, px, py, tx0, ty0, Gx, Gy)
            + dir_diff(tB, Bx, By, ao.x, ao.y, px, py, tx0, ty0, Gx, Gy);

    // Block reduction (16 warps)
    #pragma unroll
    for (int o = 16; o > 0; o >>= 1)
        s += __shfl_down_sync(0xffffffffu, s, o);
    __shared__ float shred[NT / 32];
    if ((tid & 31) == 0) shred[tid >> 5] = s;
    __syncthreads();
    if (tid < 16) {
        float v = shred[tid];
        #pragma unroll
        for (int o = 8; o > 0; o >>= 1)
            v += __shfl_down_sync(0x0000ffffu, v, o);
        if (tid == 0) {
            int bid = blockIdx.x + GX_ * (blockIdx.y + GY_ * blockIdx.z);
            g_partials[bid] = v;
        }
    }

    // Last-block-standing fused final reduce (deterministic).
    __shared__ bool amLast;
    __threadfence();
    if (tid == 0) {
        unsigned long long old = atomicAdd(&g_ticket, 1ULL);
        amLast = ((old % (unsigned long long)NBLK) == (unsigned long long)(NBLK - 1));
    }
    __syncthreads();
    if (amLast) {
        const float4* p4 = (const float4*)g_partials;  // NBLK % 4 == 0
        const int n4 = NBLK / 4;                       // 4608
        double acc = 0.0;
        for (int i = tid; i < n4; i += NT) {
            float4 v = __ldcg(p4 + i);
            acc += (double)((v.x + v.y) + (v.z + v.w));
        }
        #pragma unroll
        for (int o = 16; o > 0; o >>= 1)
            acc += __shfl_down_sync(0xffffffffu, acc, o);
        __shared__ double shd[NT / 32];
        if ((tid & 31) == 0) shd[tid >> 5] = acc;
        __syncthreads();
        if (tid < 16) {
            double v = shd[tid];
            #pragma unroll
            for (int o = 8; o > 0; o >>= 1)
                v += __shfl_down_sync(0x0000ffffu, v, o);
            if (tid == 0)
                out[0] = (float)(v / ((double)N_ * (double)HW_));
        }
    }
}

extern "C" void kernel_launch(void* const* d_in, const int* in_sizes, int n_in,
                              void* d_out, int out_size)
{
    const float* A = (const float*)d_in[0];  // UV_AtoB
    const float* B = (const float*)d_in[1];  // UV_BtoA
    dim3 block(BX, BY);
    dim3 grid(GX_, GY_, N_);
    fused_cycle_kernel<<<grid, block>>>(A, B, (float*)d_out);
}

// round 7
// speedup vs baseline: 1.8015x; 1.1333x over previous
#include <cuda_runtime.h>
#include <cuda_fp16.h>

#define W_ 768
#define H_ 768
#define N_ 16
#define HW_ (H_ * W_)
#define BX 32
#define BY 16
#define NT (BX * BY)           /* 512 */
#define R_ 8                   /* halo: covers |flow| < 8 */
#define TW 52                  /* padded tile width (mult of 4) */
#define TH (BY + 2 * R_ + 1)   /* 33 */
#define TSZ (TW * TH)          /* 1716 half2 cells */
#define NV4 (TSZ / 4)          /* 429 4-cell groups per tile */
#define GX_ (W_ / BX)          /* 24 */
#define GY_ (H_ / BY)          /* 48 */
#define NBLK (GX_ * GY_ * N_)  /* 18432 */
#define EPS2 1.0e-6f
#define INVW (1.0f / 767.0f)
#define INVH (1.0f / 767.0f)
#define WM1F 767.0f
#define HM1F 767.0f

__device__ float g_partials[NBLK];
__device__ unsigned long long g_ticket;  // monotonic across graph replays

// General m1 = warp(GridXY, flo1) at integer pixel (ix,iy): closed form.
__device__ __forceinline__ float2 m1_from(float fxv, float fyv, int ix, int iy)
{
    float gx = (float)ix + fxv;
    float gy = (float)iy + fyv;
    float x0f = floorf(gx), y0f = floorf(gy);
    float wx1 = gx - x0f, wy1 = gy - y0f;
    float wx0 = 1.0f - wx1, wy0 = 1.0f - wy1;
    int x0 = (int)x0f, y0 = (int)y0f;
    bool vx0 = ((unsigned)x0 < (unsigned)W_);
    bool vx1 = ((unsigned)(x0 + 1) < (unsigned)W_);
    bool vy0 = ((unsigned)y0 < (unsigned)H_);
    bool vy1 = ((unsigned)(y0 + 1) < (unsigned)H_);
    float c00 = (vx0 && vy0) ? wx0 * wy0 : 0.0f;
    float c10 = (vx1 && vy0) ? wx1 * wy0 : 0.0f;
    float c01 = (vx0 && vy1) ? wx0 * wy1 : 0.0f;
    float c11 = (vx1 && vy1) ? wx1 * wy1 : 0.0f;
    float m = (c00 + c10) + (c01 + c11);
    float cx1 = c10 + c11;
    float cy1 = c01 + c11;
    float ox = fmaf(m, (float)x0, cx1) * INVW;
    float oy = fmaf(m, (float)y0, cy1) * INVH;
    float M = (m < 0.9999f) ? 0.0f : 1.0f;
    return make_float2(ox * M, oy * M);
}

// General (boundary) path given the 4 corner flow float2s.
__device__ __forceinline__ float slow_eval(
    float2 f00, float2 f10, float2 f01, float2 f11,
    int x0, int y0, float wx0, float wx1, float wy0, float wy1,
    float Gx, float Gy)
{
    int x1 = x0 + 1, y1 = y0 + 1;
    bool vx0 = ((unsigned)x0 < (unsigned)W_);
    bool vx1 = ((unsigned)x1 < (unsigned)W_);
    bool vy0 = ((unsigned)y0 < (unsigned)H_);
    bool vy1 = ((unsigned)y1 < (unsigned)H_);
    float w00 = (vx0 && vy0) ? wx0 * wy0 : 0.0f;
    float w10 = (vx1 && vy0) ? wx1 * wy0 : 0.0f;
    float w01 = (vx0 && vy1) ? wx0 * wy1 : 0.0f;
    float w11 = (vx1 && vy1) ? wx1 * wy1 : 0.0f;

    float2 v00 = m1_from(f00.x, f00.y, x0, y0);
    float2 v10 = m1_from(f10.x, f10.y, x1, y0);
    float2 v01 = m1_from(f01.x, f01.y, x0, y1);
    float2 v11 = m1_from(f11.x, f11.y, x1, y1);

    float mask = (w00 + w10) + (w01 + w11);
    float mx = fmaf(w00, v00.x, fmaf(w10, v10.x, fmaf(w01, v01.x, w11 * v11.x)));
    float my = fmaf(w00, v00.y, fmaf(w10, v10.y, fmaf(w01, v01.y, w11 * v11.y)));
    float M = (mask < 0.9999f) ? 0.0f : 1.0f;
    mx *= M; my *= M;
    float dx = Gx - mx, dy = Gy - my;
    return sqrtf(fmaf(dx, dx, fmaf(dy, dy, EPS2)));
}

// One direction: second warp (by f2own, fp32) of analytic m1(f1), f1 gathered
// from the half2 tile (one LDS.32 per corner).
__device__ __forceinline__ float dir_diff(const __half2* __restrict__ t1,
                                          const float* __restrict__ g1x,
                                          const float* __restrict__ g1y,
                                          float f2x, float f2y,
                                          int px, int py, int tx0, int ty0,
                                          float Gx, float Gy)
{
    float sxf = (float)px + f2x;
    float syf = (float)py + f2y;
    float x0f = floorf(sxf), y0f = floorf(syf);
    float wx1 = sxf - x0f, wy1 = syf - y0f;
    float wx0 = 1.0f - wx1, wy0 = 1.0f - wy1;
    int x0 = (int)x0f, y0 = (int)y0f;

    int lx0 = x0 - tx0, ly0 = y0 - ty0;
    if (((unsigned)lx0 <= (unsigned)(TW - 2)) &
        ((unsigned)ly0 <= (unsigned)(TH - 2))) {
        int b = ly0 * TW + lx0;
        float2 f00 = __half22float2(t1[b]);
        float2 f10 = __half22float2(t1[b + 1]);
        float2 f01 = __half22float2(t1[b + TW]);
        float2 f11 = __half22float2(t1[b + TW + 1]);

        // Conservative interior test: outer sample in-image AND all corner
        // m1 samples in-image -> every weight/mask is 1 -> telescoped form.
        float x1f = x0f + 1.0f, y1f = y0f + 1.0f;
        float mnfx = fminf(fminf(f00.x, f01.x), fminf(f10.x, f11.x));
        float mxfx = fmaxf(fmaxf(f00.x, f01.x), fmaxf(f10.x, f11.x));
        float mnfy = fminf(fminf(f00.y, f01.y), fminf(f10.y, f11.y));
        float mxfy = fmaxf(fmaxf(f00.y, f01.y), fmaxf(f10.y, f11.y));
        bool inner = (sxf >= 0.0f) & (sxf <= WM1F) &
                     (syf >= 0.0f) & (syf <= HM1F) &
                     (x0f + mnfx >= 0.0f) & (x1f + mxfx <= WM1F) &
                     (y0f + mnfy >= 0.0f) & (y1f + mxfy <= HM1F);
        if (inner) {
            float ftx = fmaf(wx1, f10.x - f00.x, f00.x);
            float fbx = fmaf(wx1, f11.x - f01.x, f01.x);
            float bfx = fmaf(wy1, fbx - ftx, ftx);
            float fty = fmaf(wx1, f10.y - f00.y, f00.y);
            float fby = fmaf(wx1, f11.y - f01.y, f01.y);
            float bfy = fmaf(wy1, fby - fty, fty);
            float dx = (f2x + bfx) * INVW;
            float dy = (f2y + bfy) * INVH;
            return sqrtf(fmaf(dx, dx, fmaf(dy, dy, EPS2)));
        }
        return slow_eval(f00, f10, f01, f11, x0, y0, wx0, wx1, wy0, wy1, Gx, Gy);
    }
    // |f2| >= ~8: essentially never. Full clamped-global fp32 path.
    {
        int x1 = x0 + 1, y1 = y0 + 1;
        int xc0 = min(max(x0, 0), W_ - 1);
        int xc1 = min(max(x1, 0), W_ - 1);
        int yc0 = min(max(y0, 0), H_ - 1);
        int yc1 = min(max(y1, 0), H_ - 1);
        int b00 = yc0 * W_ + xc0, b10 = yc0 * W_ + xc1;
        int b01 = yc1 * W_ + xc0, b11 = yc1 * W_ + xc1;
        float2 f00 = make_float2(__ldg(g1x + b00), __ldg(g1y + b00));
        float2 f10 = make_float2(__ldg(g1x + b10), __ldg(g1y + b10));
        float2 f01 = make_float2(__ldg(g1x + b01), __ldg(g1y + b01));
        float2 f11 = make_float2(__ldg(g1x + b11), __ldg(g1y + b11));
        return slow_eval(f00, f10, f01, f11, x0, y0, wx0, wx1, wy0, wy1, Gx, Gy);
    }
}

__device__ __forceinline__ unsigned h2u(__half2 h)
{
    return *reinterpret_cast<unsigned*>(&h);
}

__global__ __launch_bounds__(NT)
void fused_cycle_kernel(const float* __restrict__ A, const float* __restrict__ B,
                        float* __restrict__ out)
{
    __shared__ __half2 tA[TSZ];
    __shared__ __half2 tB[TSZ];

    int n = blockIdx.z;
    const float* Ax = A + (size_t)n * 2 * HW_;
    const float* Ay = Ax + HW_;
    const float* Bx = B + (size_t)n * 2 * HW_;
    const float* By = Bx + HW_;

    int tx0 = blockIdx.x * BX - R_;
    int ty0 = blockIdx.y * BY - R_;
    int tid = threadIdx.y * BX + threadIdx.x;

    // Tile fill: tile cell == clamped-global value, quantized to half2.
    if (blockIdx.x >= 1 && blockIdx.x <= GX_ - 2) {
        // x-interior: [tx0, tx0+52) in-image, tx0 % 8 == 0 -> float4 loads,
        // one uint4 (=4 half2 cells) store per tile.
        if (tid < NV4) {
            int i = tid;                 // NV4 = 429 < NT, single pass
            int ly = i / (TW / 4);
            int lxg = (i - ly * (TW / 4)) * 4;
            int gy = min(max(ty0 + ly, 0), H_ - 1);
            int idx = gy * W_ + tx0 + lxg;
            float4 ax = *(const float4*)(Ax + idx);
            float4 ay = *(const float4*)(Ay + idx);
            float4 bx = *(const float4*)(Bx + idx);
            float4 by = *(const float4*)(By + idx);
            int c = ly * TW + lxg;       // c % 4 == 0 -> 16B aligned
            uint4 va = make_uint4(h2u(__floats2half2_rn(ax.x, ay.x)),
                                  h2u(__floats2half2_rn(ax.y, ay.y)),
                                  h2u(__floats2half2_rn(ax.z, ay.z)),
                                  h2u(__floats2half2_rn(ax.w, ay.w)));
            uint4 vb = make_uint4(h2u(__floats2half2_rn(bx.x, by.x)),
                                  h2u(__floats2half2_rn(bx.y, by.y)),
                                  h2u(__floats2half2_rn(bx.z, by.z)),
                                  h2u(__floats2half2_rn(bx.w, by.w)));
            *(uint4*)&tA[c] = va;
            *(uint4*)&tB[c] = vb;
        }
    } else {
        // x-edge blocks: scalar clamped fill.
        for (int i = tid; i < TSZ; i += NT) {
            int ly = i / TW, lx = i - ly * TW;
            int gx = min(max(tx0 + lx, 0), W_ - 1);
            int gy = min(max(ty0 + ly, 0), H_ - 1);
            int idx = gy * W_ + gx;
            tA[i] = __floats2half2_rn(__ldg(Ax + idx), __ldg(Ay + idx));
            tB[i] = __floats2half2_rn(__ldg(Bx + idx), __ldg(By + idx));
        }
    }

    int px = blockIdx.x * BX + threadIdx.x;
    int py = blockIdx.y * BY + threadIdx.y;
    int idx = py * W_ + px;
    // Own-pixel flows from global at full fp32 precision (coalesced).
    float aox = __ldg(Ax + idx);
    float aoy = __ldg(Ay + idx);
    float box = __ldg(Bx + idx);
    float boy = __ldg(By + idx);

    __syncthreads();

    float Gx = (float)px * INVW;
    float Gy = (float)py * INVH;

    // ABA: gather A at corners of p+B(p).  BAB: gather B at corners of p+A(p).
    float s = dir_diff(tA, Ax, Ay, box, boy, px, py, tx0, ty0, Gx, Gy)
            + dir_diff(tB, Bx, By, aox, aoy, px, py, tx0, ty0, Gx, Gy);

    // Block reduction (16 warps)
    #pragma unroll
    for (int o = 16; o > 0; o >>= 1)
        s += __shfl_down_sync(0xffffffffu, s, o);
    __shared__ float shred[NT / 32];
    if ((tid & 31) == 0) shred[tid >> 5] = s;
    __syncthreads();
    if (tid < 16) {
        float v = shred[tid];
        #pragma unroll
        for (int o = 8; o > 0; o >>= 1)
            v += __shfl_down_sync(0x0000ffffu, v, o);
        if (tid == 0) {
            int bid = blockIdx.x + GX_ * (blockIdx.y + GY_ * blockIdx.z);
            g_partials[bid] = v;
        }
    }

    // Last-block-standing fused final reduce (deterministic).
    __shared__ bool amLast;
    __threadfence();
    if (tid == 0) {
        unsigned long long old = atomicAdd(&g_ticket, 1ULL);
        amLast = ((old % (unsigned long long)NBLK) == (unsigned long long)(NBLK - 1));
    }
    __syncthreads();
    if (amLast) {
        const float4* p4 = (const float4*)g_partials;  // NBLK % 4 == 0
        const int n4 = NBLK / 4;                       // 4608
        double acc = 0.0;
        for (int i = tid; i < n4; i += NT) {
            float4 v = __ldcg(p4 + i);
            acc += (double)((v.x + v.y) + (v.z + v.w));
        }
        #pragma unroll
        for (int o = 16; o > 0; o >>= 1)
            acc += __shfl_down_sync(0xffffffffu, acc, o);
        __shared__ double shd[NT / 32];
        if ((tid & 31) == 0) shd[tid >> 5] = acc;
        __syncthreads();
        if (tid < 16) {
            double v = shd[tid];
            #pragma unroll
            for (int o = 8; o > 0; o >>= 1)
                v += __shfl_down_sync(0x0000ffffu, v, o);
            if (tid == 0)
                out[0] = (float)(v / ((double)N_ * (double)HW_));
        }
    }
}

extern "C" void kernel_launch(void* const* d_in, const int* in_sizes, int n_in,
                              void* d_out, int out_size)
{
    const float* A = (const float*)d_in[0];  // UV_AtoB
    const float* B = (const float*)d_in[1];  // UV_BtoA
    dim3 block(BX, BY);
    dim3 grid(GX_, GY_, N_);
    fused_cycle_kernel<<<grid, block>>>(A, B, (float*)d_out);
}

// round 8
// speedup vs baseline: 2.0831x; 1.1563x over previous
#include <cuda_runtime.h>
#include <cuda_fp16.h>

#define W_ 768
#define H_ 768
#define N_ 16
#define HW_ (H_ * W_)
#define BX 32
#define BY 16
#define NT (BX * BY)           /* 512 */
#define RPB 32                 /* pixel rows per block (2 per thread) */
#define R_ 8                   /* halo: covers |flow| < 8 */
#define TW 52                  /* padded tile width (mult of 4) */
#define TH (RPB + 2 * R_ + 1)  /* 49 */
#define TSZ (TW * TH)          /* 2548 half2 cells */
#define NV4 (TSZ / 4)          /* 637 4-cell groups per tile */
#define GX_ (W_ / BX)          /* 24 */
#define GY_ (H_ / RPB)         /* 24 */
#define NBLK (GX_ * GY_ * N_)  /* 9216 */
#define EPS2 1.0e-6f
#define INVW (1.0f / 767.0f)
#define INVH (1.0f / 767.0f)
#define WM1F 767.0f
#define HM1F 767.0f

__device__ float g_partials[NBLK];
__device__ unsigned long long g_ticket;  // monotonic across graph replays

// General m1 = warp(GridXY, flo1) at integer pixel (ix,iy): closed form.
__device__ __forceinline__ float2 m1_from(float fxv, float fyv, int ix, int iy)
{
    float gx = (float)ix + fxv;
    float gy = (float)iy + fyv;
    float x0f = floorf(gx), y0f = floorf(gy);
    float wx1 = gx - x0f, wy1 = gy - y0f;
    float wx0 = 1.0f - wx1, wy0 = 1.0f - wy1;
    int x0 = (int)x0f, y0 = (int)y0f;
    bool vx0 = ((unsigned)x0 < (unsigned)W_);
    bool vx1 = ((unsigned)(x0 + 1) < (unsigned)W_);
    bool vy0 = ((unsigned)y0 < (unsigned)H_);
    bool vy1 = ((unsigned)(y0 + 1) < (unsigned)H_);
    float c00 = (vx0 && vy0) ? wx0 * wy0 : 0.0f;
    float c10 = (vx1 && vy0) ? wx1 * wy0 : 0.0f;
    float c01 = (vx0 && vy1) ? wx0 * wy1 : 0.0f;
    float c11 = (vx1 && vy1) ? wx1 * wy1 : 0.0f;
    float m = (c00 + c10) + (c01 + c11);
    float cx1 = c10 + c11;
    float cy1 = c01 + c11;
    float ox = fmaf(m, (float)x0, cx1) * INVW;
    float oy = fmaf(m, (float)y0, cy1) * INVH;
    float M = (m < 0.9999f) ? 0.0f : 1.0f;
    return make_float2(ox * M, oy * M);
}

// General (boundary) path given the 4 corner flow float2s.
__device__ __forceinline__ float slow_eval(
    float2 f00, float2 f10, float2 f01, float2 f11,
    int x0, int y0, float wx0, float wx1, float wy0, float wy1,
    float Gx, float Gy)
{
    int x1 = x0 + 1, y1 = y0 + 1;
    bool vx0 = ((unsigned)x0 < (unsigned)W_);
    bool vx1 = ((unsigned)x1 < (unsigned)W_);
    bool vy0 = ((unsigned)y0 < (unsigned)H_);
    bool vy1 = ((unsigned)y1 < (unsigned)H_);
    float w00 = (vx0 && vy0) ? wx0 * wy0 : 0.0f;
    float w10 = (vx1 && vy0) ? wx1 * wy0 : 0.0f;
    float w01 = (vx0 && vy1) ? wx0 * wy1 : 0.0f;
    float w11 = (vx1 && vy1) ? wx1 * wy1 : 0.0f;

    float2 v00 = m1_from(f00.x, f00.y, x0, y0);
    float2 v10 = m1_from(f10.x, f10.y, x1, y0);
    float2 v01 = m1_from(f01.x, f01.y, x0, y1);
    float2 v11 = m1_from(f11.x, f11.y, x1, y1);

    float mask = (w00 + w10) + (w01 + w11);
    float mx = fmaf(w00, v00.x, fmaf(w10, v10.x, fmaf(w01, v01.x, w11 * v11.x)));
    float my = fmaf(w00, v00.y, fmaf(w10, v10.y, fmaf(w01, v01.y, w11 * v11.y)));
    float M = (mask < 0.9999f) ? 0.0f : 1.0f;
    mx *= M; my *= M;
    float dx = Gx - mx, dy = Gy - my;
    return sqrtf(fmaf(dx, dx, fmaf(dy, dy, EPS2)));
}

// One direction: second warp (by f2own, fp32) of analytic m1(f1), f1 gathered
// from the half2 tile (one LDS.32 per corner).
__device__ __forceinline__ float dir_diff(const __half2* __restrict__ t1,
                                          const float* __restrict__ g1x,
                                          const float* __restrict__ g1y,
                                          float f2x, float f2y,
                                          int px, int py, int tx0, int ty0,
                                          float Gx, float Gy)
{
    float sxf = (float)px + f2x;
    float syf = (float)py + f2y;
    float x0f = floorf(sxf), y0f = floorf(syf);
    float wx1 = sxf - x0f, wy1 = syf - y0f;
    float wx0 = 1.0f - wx1, wy0 = 1.0f - wy1;
    int x0 = (int)x0f, y0 = (int)y0f;

    int lx0 = x0 - tx0, ly0 = y0 - ty0;
    if (((unsigned)lx0 <= (unsigned)(TW - 2)) &
        ((unsigned)ly0 <= (unsigned)(TH - 2))) {
        int b = ly0 * TW + lx0;
        float2 f00 = __half22float2(t1[b]);
        float2 f10 = __half22float2(t1[b + 1]);
        float2 f01 = __half22float2(t1[b + TW]);
        float2 f11 = __half22float2(t1[b + TW + 1]);

        // Conservative interior test: outer sample in-image AND all corner
        // m1 samples in-image -> every weight/mask is 1 -> telescoped form.
        float x1f = x0f + 1.0f, y1f = y0f + 1.0f;
        float mnfx = fminf(fminf(f00.x, f01.x), fminf(f10.x, f11.x));
        float mxfx = fmaxf(fmaxf(f00.x, f01.x), fmaxf(f10.x, f11.x));
        float mnfy = fminf(fminf(f00.y, f01.y), fminf(f10.y, f11.y));
        float mxfy = fmaxf(fmaxf(f00.y, f01.y), fmaxf(f10.y, f11.y));
        bool inner = (sxf >= 0.0f) & (sxf <= WM1F) &
                     (syf >= 0.0f) & (syf <= HM1F) &
                     (x0f + mnfx >= 0.0f) & (x1f + mxfx <= WM1F) &
                     (y0f + mnfy >= 0.0f) & (y1f + mxfy <= HM1F);
        if (inner) {
            float ftx = fmaf(wx1, f10.x - f00.x, f00.x);
            float fbx = fmaf(wx1, f11.x - f01.x, f01.x);
            float bfx = fmaf(wy1, fbx - ftx, ftx);
            float fty = fmaf(wx1, f10.y - f00.y, f00.y);
            float fby = fmaf(wx1, f11.y - f01.y, f01.y);
            float bfy = fmaf(wy1, fby - fty, fty);
            float dx = (f2x + bfx) * INVW;
            float dy = (f2y + bfy) * INVH;
            return sqrtf(fmaf(dx, dx, fmaf(dy, dy, EPS2)));
        }
        return slow_eval(f00, f10, f01, f11, x0, y0, wx0, wx1, wy0, wy1, Gx, Gy);
    }
    // |f2| >= ~8: essentially never. Full clamped-global fp32 path.
    {
        int x1 = x0 + 1, y1 = y0 + 1;
        int xc0 = min(max(x0, 0), W_ - 1);
        int xc1 = min(max(x1, 0), W_ - 1);
        int yc0 = min(max(y0, 0), H_ - 1);
        int yc1 = min(max(y1, 0), H_ - 1);
        int b00 = yc0 * W_ + xc0, b10 = yc0 * W_ + xc1;
        int b01 = yc1 * W_ + xc0, b11 = yc1 * W_ + xc1;
        float2 f00 = make_float2(__ldg(g1x + b00), __ldg(g1y + b00));
        float2 f10 = make_float2(__ldg(g1x + b10), __ldg(g1y + b10));
        float2 f01 = make_float2(__ldg(g1x + b01), __ldg(g1y + b01));
        float2 f11 = make_float2(__ldg(g1x + b11), __ldg(g1y + b11));
        return slow_eval(f00, f10, f01, f11, x0, y0, wx0, wx1, wy0, wy1, Gx, Gy);
    }
}

__device__ __forceinline__ unsigned h2u(__half2 h)
{
    return *reinterpret_cast<unsigned*>(&h);
}

__global__ __launch_bounds__(NT)
void fused_cycle_kernel(const float* __restrict__ A, const float* __restrict__ B,
                        float* __restrict__ out)
{
    __shared__ __half2 tA[TSZ];
    __shared__ __half2 tB[TSZ];

    int n = blockIdx.z;
    const float* Ax = A + (size_t)n * 2 * HW_;
    const float* Ay = Ax + HW_;
    const float* Bx = B + (size_t)n * 2 * HW_;
    const float* By = Bx + HW_;

    int tx0 = blockIdx.x * BX - R_;
    int ty0 = blockIdx.y * RPB - R_;
    int tid = threadIdx.y * BX + threadIdx.x;

    // Tile fill: tile cell == clamped-global value, quantized to half2.
    if (blockIdx.x >= 1 && blockIdx.x <= GX_ - 2) {
        // x-interior: [tx0, tx0+52) in-image, tx0 % 8 == 0 -> float4 loads,
        // one uint4 (=4 half2 cells) store per tile.
        for (int i = tid; i < NV4; i += NT) {
            int ly = i / (TW / 4);
            int lxg = (i - ly * (TW / 4)) * 4;
            int gy = min(max(ty0 + ly, 0), H_ - 1);
            int idx = gy * W_ + tx0 + lxg;
            float4 ax = *(const float4*)(Ax + idx);
            float4 ay = *(const float4*)(Ay + idx);
            float4 bx = *(const float4*)(Bx + idx);
            float4 by = *(const float4*)(By + idx);
            int c = ly * TW + lxg;       // c % 4 == 0 -> 16B aligned
            uint4 va = make_uint4(h2u(__floats2half2_rn(ax.x, ay.x)),
                                  h2u(__floats2half2_rn(ax.y, ay.y)),
                                  h2u(__floats2half2_rn(ax.z, ay.z)),
                                  h2u(__floats2half2_rn(ax.w, ay.w)));
            uint4 vb = make_uint4(h2u(__floats2half2_rn(bx.x, by.x)),
                                  h2u(__floats2half2_rn(bx.y, by.y)),
                                  h2u(__floats2half2_rn(bx.z, by.z)),
                                  h2u(__floats2half2_rn(bx.w, by.w)));
            *(uint4*)&tA[c] = va;
            *(uint4*)&tB[c] = vb;
        }
    } else {
        // x-edge blocks: scalar clamped fill.
        for (int i = tid; i < TSZ; i += NT) {
            int ly = i / TW, lx = i - ly * TW;
            int gx = min(max(tx0 + lx, 0), W_ - 1);
            int gy = min(max(ty0 + ly, 0), H_ - 1);
            int idx = gy * W_ + gx;
            tA[i] = __floats2half2_rn(__ldg(Ax + idx), __ldg(Ay + idx));
            tB[i] = __floats2half2_rn(__ldg(Bx + idx), __ldg(By + idx));
        }
    }

    int px = blockIdx.x * BX + threadIdx.x;
    int py0 = blockIdx.y * RPB + threadIdx.y;        // row 0
    int py1 = py0 + BY;                              // row 1 (16 apart)
    int idx0 = py0 * W_ + px;
    int idx1 = py1 * W_ + px;
    // Own-pixel flows from global at full fp32 precision (coalesced).
    float aox0 = __ldg(Ax + idx0), aoy0 = __ldg(Ay + idx0);
    float box0 = __ldg(Bx + idx0), boy0 = __ldg(By + idx0);
    float aox1 = __ldg(Ax + idx1), aoy1 = __ldg(Ay + idx1);
    float box1 = __ldg(Bx + idx1), boy1 = __ldg(By + idx1);

    __syncthreads();

    float Gx  = (float)px  * INVW;
    float Gy0 = (float)py0 * INVH;
    float Gy1 = (float)py1 * INVH;

    // Per row: ABA gathers A at corners of p+B(p); BAB gathers B at p+A(p).
    float s = dir_diff(tA, Ax, Ay, box0, boy0, px, py0, tx0, ty0, Gx, Gy0)
            + dir_diff(tB, Bx, By, aox0, aoy0, px, py0, tx0, ty0, Gx, Gy0)
            + dir_diff(tA, Ax, Ay, box1, boy1, px, py1, tx0, ty0, Gx, Gy1)
            + dir_diff(tB, Bx, By, aox1, aoy1, px, py1, tx0, ty0, Gx, Gy1);

    // Block reduction (16 warps)
    #pragma unroll
    for (int o = 16; o > 0; o >>= 1)
        s += __shfl_down_sync(0xffffffffu, s, o);
    __shared__ float shred[NT / 32];
    if ((tid & 31) == 0) shred[tid >> 5] = s;
    __syncthreads();
    if (tid < 16) {
        float v = shred[tid];
        #pragma unroll
        for (int o = 8; o > 0; o >>= 1)
            v += __shfl_down_sync(0x0000ffffu, v, o);
        if (tid == 0) {
            int bid = blockIdx.x + GX_ * (blockIdx.y + GY_ * blockIdx.z);
            g_partials[bid] = v;
        }
    }

    // Last-block-standing fused final reduce (deterministic).
    __shared__ bool amLast;
    __threadfence();
    if (tid == 0) {
        unsigned long long old = atomicAdd(&g_ticket, 1ULL);
        amLast = ((old % (unsigned long long)NBLK) == (unsigned long long)(NBLK - 1));
    }
    __syncthreads();
    if (amLast) {
        const float4* p4 = (const float4*)g_partials;  // NBLK % 4 == 0
        const int n4 = NBLK / 4;                       // 2304
        double acc = 0.0;
        for (int i = tid; i < n4; i += NT) {
            float4 v = __ldcg(p4 + i);
            acc += (double)((v.x + v.y) + (v.z + v.w));
        }
        #pragma unroll
        for (int o = 16; o > 0; o >>= 1)
            acc += __shfl_down_sync(0xffffffffu, acc, o);
        __shared__ double shd[NT / 32];
        if ((tid & 31) == 0) shd[tid >> 5] = acc;
        __syncthreads();
        if (tid < 16) {
            double v = shd[tid];
            #pragma unroll
            for (int o = 8; o > 0; o >>= 1)
                v += __shfl_down_sync(0x0000ffffu, v, o);
            if (tid == 0)
                out[0] = (float)(v / ((double)N_ * (double)HW_));
        }
    }
}

extern "C" void kernel_launch(void* const* d_in, const int* in_sizes, int n_in,
                              void* d_out, int out_size)
{
    const float* A = (const float*)d_in[0];  // UV_AtoB
    const float* B = (const float*)d_in[1];  // UV_BtoA
    dim3 block(BX, BY);
    dim3 grid(GX_, GY_, N_);
    fused_cycle_kernel<<<grid, block>>>(A, B, (float*)d_out);
}

// round 9
// speedup vs baseline: 2.2373x; 1.0740x over previous
#include <cuda_runtime.h>
#include <cuda_fp16.h>

#define W_ 768
#define H_ 768
#define N_ 16
#define HW_ (H_ * W_)
#define BX 32
#define BY 16
#define NT (BX * BY)           /* 512 */
#define RPB 32                 /* pixel rows per block (2 per thread) */
#define R_ 8                   /* halo: covers |flow| < 8 */
#define TW 52                  /* padded tile width (mult of 4) */
#define TH (RPB + 2 * R_ + 1)  /* 49 */
#define TSZ (TW * TH)          /* 2548 half2 cells */
#define NV4 (TSZ / 4)          /* 637 4-cell groups per tile */
#define GX_ (W_ / BX)          /* 24 */
#define GY_ (H_ / RPB)         /* 24 */
#define NBLK (GX_ * GY_ * N_)  /* 9216 */
#define EPS2 1.0e-6f
#define INVW (1.0f / 767.0f)
#define INVH (1.0f / 767.0f)
#define WM1F 767.0f
#define HM1F 767.0f
#define CLEAN_TH 6.98f

__device__ float g_partials[NBLK];
__device__ unsigned long long g_ticket;  // monotonic across graph replays

// General m1 = warp(GridXY, flo1) at integer pixel (ix,iy): closed form.
__device__ __forceinline__ float2 m1_from(float fxv, float fyv, int ix, int iy)
{
    float gx = (float)ix + fxv;
    float gy = (float)iy + fyv;
    float x0f = floorf(gx), y0f = floorf(gy);
    float wx1 = gx - x0f, wy1 = gy - y0f;
    float wx0 = 1.0f - wx1, wy0 = 1.0f - wy1;
    int x0 = (int)x0f, y0 = (int)y0f;
    bool vx0 = ((unsigned)x0 < (unsigned)W_);
    bool vx1 = ((unsigned)(x0 + 1) < (unsigned)W_);
    bool vy0 = ((unsigned)y0 < (unsigned)H_);
    bool vy1 = ((unsigned)(y0 + 1) < (unsigned)H_);
    float c00 = (vx0 && vy0) ? wx0 * wy0 : 0.0f;
    float c10 = (vx1 && vy0) ? wx1 * wy0 : 0.0f;
    float c01 = (vx0 && vy1) ? wx0 * wy1 : 0.0f;
    float c11 = (vx1 && vy1) ? wx1 * wy1 : 0.0f;
    float m = (c00 + c10) + (c01 + c11);
    float cx1 = c10 + c11;
    float cy1 = c01 + c11;
    float ox = fmaf(m, (float)x0, cx1) * INVW;
    float oy = fmaf(m, (float)y0, cy1) * INVH;
    float M = (m < 0.9999f) ? 0.0f : 1.0f;
    return make_float2(ox * M, oy * M);
}

// General (boundary) path given the 4 corner flow float2s.
__device__ __forceinline__ float slow_eval(
    float2 f00, float2 f10, float2 f01, float2 f11,
    int x0, int y0, float wx0, float wx1, float wy0, float wy1,
    float Gx, float Gy)
{
    int x1 = x0 + 1, y1 = y0 + 1;
    bool vx0 = ((unsigned)x0 < (unsigned)W_);
    bool vx1 = ((unsigned)x1 < (unsigned)W_);
    bool vy0 = ((unsigned)y0 < (unsigned)H_);
    bool vy1 = ((unsigned)y1 < (unsigned)H_);
    float w00 = (vx0 && vy0) ? wx0 * wy0 : 0.0f;
    float w10 = (vx1 && vy0) ? wx1 * wy0 : 0.0f;
    float w01 = (vx0 && vy1) ? wx0 * wy1 : 0.0f;
    float w11 = (vx1 && vy1) ? wx1 * wy1 : 0.0f;

    float2 v00 = m1_from(f00.x, f00.y, x0, y0);
    float2 v10 = m1_from(f10.x, f10.y, x1, y0);
    float2 v01 = m1_from(f01.x, f01.y, x0, y1);
    float2 v11 = m1_from(f11.x, f11.y, x1, y1);

    float mask = (w00 + w10) + (w01 + w11);
    float mx = fmaf(w00, v00.x, fmaf(w10, v10.x, fmaf(w01, v01.x, w11 * v11.x)));
    float my = fmaf(w00, v00.y, fmaf(w10, v10.y, fmaf(w01, v01.y, w11 * v11.y)));
    float M = (mask < 0.9999f) ? 0.0f : 1.0f;
    mx *= M; my *= M;
    float dx = Gx - mx, dy = Gy - my;
    return sqrtf(fmaf(dx, dx, fmaf(dy, dy, EPS2)));
}

// General per-pixel path (edge/dirty blocks): tile guard + interior test +
// boundary math + rare clamped-global fallback. Identical to R8.
__device__ __forceinline__ float dir_diff(const __half2* __restrict__ t1,
                                          const float* __restrict__ g1x,
                                          const float* __restrict__ g1y,
                                          float f2x, float f2y,
                                          int px, int py, int tx0, int ty0,
                                          float Gx, float Gy)
{
    float sxf = (float)px + f2x;
    float syf = (float)py + f2y;
    float x0f = floorf(sxf), y0f = floorf(syf);
    float wx1 = sxf - x0f, wy1 = syf - y0f;
    float wx0 = 1.0f - wx1, wy0 = 1.0f - wy1;
    int x0 = (int)x0f, y0 = (int)y0f;

    int lx0 = x0 - tx0, ly0 = y0 - ty0;
    if (((unsigned)lx0 <= (unsigned)(TW - 2)) &
        ((unsigned)ly0 <= (unsigned)(TH - 2))) {
        int b = ly0 * TW + lx0;
        float2 f00 = __half22float2(t1[b]);
        float2 f10 = __half22float2(t1[b + 1]);
        float2 f01 = __half22float2(t1[b + TW]);
        float2 f11 = __half22float2(t1[b + TW + 1]);

        float x1f = x0f + 1.0f, y1f = y0f + 1.0f;
        float mnfx = fminf(fminf(f00.x, f01.x), fminf(f10.x, f11.x));
        float mxfx = fmaxf(fmaxf(f00.x, f01.x), fmaxf(f10.x, f11.x));
        float mnfy = fminf(fminf(f00.y, f01.y), fminf(f10.y, f11.y));
        float mxfy = fmaxf(fmaxf(f00.y, f01.y), fmaxf(f10.y, f11.y));
        bool inner = (sxf >= 0.0f) & (sxf <= WM1F) &
                     (syf >= 0.0f) & (syf <= HM1F) &
                     (x0f + mnfx >= 0.0f) & (x1f + mxfx <= WM1F) &
                     (y0f + mnfy >= 0.0f) & (y1f + mxfy <= HM1F);
        if (inner) {
            float ftx = fmaf(wx1, f10.x - f00.x, f00.x);
            float fbx = fmaf(wx1, f11.x - f01.x, f01.x);
            float bfx = fmaf(wy1, fbx - ftx, ftx);
            float fty = fmaf(wx1, f10.y - f00.y, f00.y);
            float fby = fmaf(wx1, f11.y - f01.y, f01.y);
            float bfy = fmaf(wy1, fby - fty, fty);
            float dx = (f2x + bfx) * INVW;
            float dy = (f2y + bfy) * INVH;
            return sqrtf(fmaf(dx, dx, fmaf(dy, dy, EPS2)));
        }
        return slow_eval(f00, f10, f01, f11, x0, y0, wx0, wx1, wy0, wy1, Gx, Gy);
    }
    {
        int x1 = x0 + 1, y1 = y0 + 1;
        int xc0 = min(max(x0, 0), W_ - 1);
        int xc1 = min(max(x1, 0), W_ - 1);
        int yc0 = min(max(y0, 0), H_ - 1);
        int yc1 = min(max(y1, 0), H_ - 1);
        int b00 = yc0 * W_ + xc0, b10 = yc0 * W_ + xc1;
        int b01 = yc1 * W_ + xc0, b11 = yc1 * W_ + xc1;
        float2 f00 = make_float2(__ldg(g1x + b00), __ldg(g1y + b00));
        float2 f10 = make_float2(__ldg(g1x + b10), __ldg(g1y + b10));
        float2 f01 = make_float2(__ldg(g1x + b01), __ldg(g1y + b01));
        float2 f11 = make_float2(__ldg(g1x + b11), __ldg(g1y + b11));
        return slow_eval(f00, f10, f01, f11, x0, y0, wx0, wx1, wy0, wy1, Gx, Gy);
    }
}

// Clean-block fast path: unconditional telescoped form, bilerp in half2.
// Valid when the whole block is interior-margin and all |flow| < 7 (proven
// by the block-level clean check): every mask/validity term is 1.
__device__ __forceinline__ float dir_fast(const __half2* __restrict__ t1,
                                          float f2x, float f2y,
                                          int px, int py, int tx0, int ty0)
{
    float sxf = (float)px + f2x;
    float syf = (float)py + f2y;
    float x0f = floorf(sxf), y0f = floorf(syf);
    float wx1 = sxf - x0f, wy1 = syf - y0f;
    int b = ((int)y0f - ty0) * TW + ((int)x0f - tx0);

    __half2 f00 = t1[b];
    __half2 f10 = t1[b + 1];
    __half2 f01 = t1[b + TW];
    __half2 f11 = t1[b + TW + 1];

    __half2 hx1 = __float2half2_rn(wx1);
    __half2 hx0 = __float2half2_rn(1.0f - wx1);
    __half2 hy1 = __float2half2_rn(wy1);
    __half2 hy0 = __float2half2_rn(1.0f - wy1);

    __half2 top = __hfma2(f10, hx1, __hmul2(f00, hx0));
    __half2 bot = __hfma2(f11, hx1, __hmul2(f01, hx0));
    __half2 r   = __hfma2(bot, hy1, __hmul2(top, hy0));
    float2 bf = __half22float2(r);

    float dx = (f2x + bf.x) * INVW;
    float dy = (f2y + bf.y) * INVH;
    return sqrtf(fmaf(dx, dx, fmaf(dy, dy, EPS2)));
}

__device__ __forceinline__ unsigned h2u(__half2 h)
{
    return *reinterpret_cast<unsigned*>(&h);
}

__global__ __launch_bounds__(NT)
void fused_cycle_kernel(const float* __restrict__ A, const float* __restrict__ B,
                        float* __restrict__ out)
{
    __shared__ __half2 tA[TSZ];
    __shared__ __half2 tB[TSZ];

    int n = blockIdx.z;
    const float* Ax = A + (size_t)n * 2 * HW_;
    const float* Ay = Ax + HW_;
    const float* Bx = B + (size_t)n * 2 * HW_;
    const float* By = Bx + HW_;

    int tx0 = blockIdx.x * BX - R_;
    int ty0 = blockIdx.y * RPB - R_;
    int tid = threadIdx.y * BX + threadIdx.x;

    // Edge blocks can never take the block-fast path (image-margin condition).
    bool edgeBlk = (blockIdx.x < 1) | (blockIdx.x > GX_ - 2) |
                   (blockIdx.y < 1) | (blockIdx.y > GY_ - 2);
    int dirty = edgeBlk ? 1 : 0;

    // Tile fill: tile cell == clamped-global value, quantized to half2.
    if (blockIdx.x >= 1 && blockIdx.x <= GX_ - 2) {
        for (int i = tid; i < NV4; i += NT) {
            int ly = i / (TW / 4);
            int lxg = (i - ly * (TW / 4)) * 4;
            int gy = min(max(ty0 + ly, 0), H_ - 1);
            int idx = gy * W_ + tx0 + lxg;
            float4 ax = *(const float4*)(Ax + idx);
            float4 ay = *(const float4*)(Ay + idx);
            float4 bx = *(const float4*)(Bx + idx);
            float4 by = *(const float4*)(By + idx);
            // Clean check on fp32 values before quantization.
            float ma = fmaxf(fmaxf(fmaxf(fabsf(ax.x), fabsf(ax.y)),
                                   fmaxf(fabsf(ax.z), fabsf(ax.w))),
                             fmaxf(fmaxf(fabsf(ay.x), fabsf(ay.y)),
                                   fmaxf(fabsf(ay.z), fabsf(ay.w))));
            float mb = fmaxf(fmaxf(fmaxf(fabsf(bx.x), fabsf(bx.y)),
                                   fmaxf(fabsf(bx.z), fabsf(bx.w))),
                             fmaxf(fmaxf(fabsf(by.x), fabsf(by.y)),
                                   fmaxf(fabsf(by.z), fabsf(by.w))));
            if (fmaxf(ma, mb) >= CLEAN_TH) dirty = 1;
            int c = ly * TW + lxg;       // c % 4 == 0 -> 16B aligned
            uint4 va = make_uint4(h2u(__floats2half2_rn(ax.x, ay.x)),
                                  h2u(__floats2half2_rn(ax.y, ay.y)),
                                  h2u(__floats2half2_rn(ax.z, ay.z)),
                                  h2u(__floats2half2_rn(ax.w, ay.w)));
            uint4 vb = make_uint4(h2u(__floats2half2_rn(bx.x, by.x)),
                                  h2u(__floats2half2_rn(bx.y, by.y)),
                                  h2u(__floats2half2_rn(bx.z, by.z)),
                                  h2u(__floats2half2_rn(bx.w, by.w)));
            *(uint4*)&tA[c] = va;
            *(uint4*)&tB[c] = vb;
        }
    } else {
        for (int i = tid; i < TSZ; i += NT) {
            int ly = i / TW, lx = i - ly * TW;
            int gx = min(max(tx0 + lx, 0), W_ - 1);
            int gy = min(max(ty0 + ly, 0), H_ - 1);
            int idx = gy * W_ + gx;
            tA[i] = __floats2half2_rn(__ldg(Ax + idx), __ldg(Ay + idx));
            tB[i] = __floats2half2_rn(__ldg(Bx + idx), __ldg(By + idx));
        }
    }

    int px = blockIdx.x * BX + threadIdx.x;
    int py0 = blockIdx.y * RPB + threadIdx.y;        // row 0
    int py1 = py0 + BY;                              // row 1 (16 apart)
    int idx0 = py0 * W_ + px;
    int idx1 = py1 * W_ + px;
    float aox0 = __ldg(Ax + idx0), aoy0 = __ldg(Ay + idx0);
    float box0 = __ldg(Bx + idx0), boy0 = __ldg(By + idx0);
    float aox1 = __ldg(Ax + idx1), aoy1 = __ldg(Ay + idx1);
    float box1 = __ldg(Bx + idx1), boy1 = __ldg(By + idx1);

    bool fastBlk = (__syncthreads_or(dirty) == 0);   // also the fill barrier

    float s;
    if (fastBlk) {
        s = dir_fast(tA, box0, boy0, px, py0, tx0, ty0)
          + dir_fast(tB, aox0, aoy0, px, py0, tx0, ty0)
          + dir_fast(tA, box1, boy1, px, py1, tx0, ty0)
          + dir_fast(tB, aox1, aoy1, px, py1, tx0, ty0);
    } else {
        float Gx  = (float)px  * INVW;
        float Gy0 = (float)py0 * INVH;
        float Gy1 = (float)py1 * INVH;
        s = dir_diff(tA, Ax, Ay, box0, boy0, px, py0, tx0, ty0, Gx, Gy0)
          + dir_diff(tB, Bx, By, aox0, aoy0, px, py0, tx0, ty0, Gx, Gy0)
          + dir_diff(tA, Ax, Ay, box1, boy1, px, py1, tx0, ty0, Gx, Gy1)
          + dir_diff(tB, Bx, By, aox1, aoy1, px, py1, tx0, ty0, Gx, Gy1);
    }

    // Block reduction (16 warps)
    #pragma unroll
    for (int o = 16; o > 0; o >>= 1)
        s += __shfl_down_sync(0xffffffffu, s, o);
    __shared__ float shred[NT / 32];
    if ((tid & 31) == 0) shred[tid >> 5] = s;
    __syncthreads();
    if (tid < 16) {
        float v = shred[tid];
        #pragma unroll
        for (int o = 8; o > 0; o >>= 1)
            v += __shfl_down_sync(0x0000ffffu, v, o);
        if (tid == 0) {
            int bid = blockIdx.x + GX_ * (blockIdx.y + GY_ * blockIdx.z);
            g_partials[bid] = v;
        }
    }

    // Last-block-standing fused final reduce (deterministic).
    __shared__ bool amLast;
    __threadfence();
    if (tid == 0) {
        unsigned long long old = atomicAdd(&g_ticket, 1ULL);
        amLast = ((old % (unsigned long long)NBLK) == (unsigned long long)(NBLK - 1));
    }
    __syncthreads();
    if (amLast) {
        const float4* p4 = (const float4*)g_partials;  // NBLK % 4 == 0
        const int n4 = NBLK / 4;                       // 2304
        double acc = 0.0;
        for (int i = tid; i < n4; i += NT) {
            float4 v = __ldcg(p4 + i);
            acc += (double)((v.x + v.y) + (v.z + v.w));
        }
        #pragma unroll
        for (int o = 16; o > 0; o >>= 1)
            acc += __shfl_down_sync(0xffffffffu, acc, o);
        __shared__ double shd[NT / 32];
        if ((tid & 31) == 0) shd[tid >> 5] = acc;
        __syncthreads();
        if (tid < 16) {
            double v = shd[tid];
            #pragma unroll
            for (int o = 8; o > 0; o >>= 1)
                v += __shfl_down_sync(0x0000ffffu, v, o);
            if (tid == 0)
                out[0] = (float)(v / ((double)N_ * (double)HW_));
        }
    }
}

extern "C" void kernel_launch(void* const* d_in, const int* in_sizes, int n_in,
                              void* d_out, int out_size)
{
    const float* A = (const float*)d_in[0];  // UV_AtoB
    const float* B = (const float*)d_in[1];  // UV_BtoA
    dim3 block(BX, BY);
    dim3 grid(GX_, GY_, N_);
    fused_cycle_kernel<<<grid, block>>>(A, B, (float*)d_out);
}

// round 10
// speedup vs baseline: 2.3327x; 1.0426x over previous
#include <cuda_runtime.h>
#include <cuda_fp16.h>

#define W_ 768
#define H_ 768
#define N_ 16
#define HW_ (H_ * W_)
#define BX 32
#define BY 16
#define NT (BX * BY)           /* 512 */
#define RPB 32                 /* pixel rows per block (2 per thread) */
#define R_ 8                   /* halo: covers |flow| < 8 */
#define TW 52                  /* padded tile width (mult of 4) */
#define TH (RPB + 2 * R_ + 1)  /* 49 */
#define TSZ (TW * TH)          /* 2548 half2 cells */
#define NV4 (TSZ / 4)          /* 637 4-cell groups per tile */
#define GX_ (W_ / BX)          /* 24 */
#define GY_ (H_ / RPB)         /* 24 */
#define NBLK (GX_ * GY_ * N_)  /* 9216 */
#define EPS2 1.0e-6f
#define INVW (1.0f / 767.0f)
#define INVH (1.0f / 767.0f)
#define WM1F 767.0f
#define HM1F 767.0f
#define CLEAN_TH 6.98f

__device__ float g_partials[NBLK];
__device__ unsigned long long g_ticket;  // monotonic across graph replays

// v >= EPS2 > 0 always; MUFU.RSQ + FMUL instead of IEEE sqrt sequence.
__device__ __forceinline__ float fast_sqrt(float v)
{
    return v * __frsqrt_rn(v);
}

// General m1 = warp(GridXY, flo1) at integer pixel (ix,iy): closed form.
__device__ __forceinline__ float2 m1_from(float fxv, float fyv, int ix, int iy)
{
    float gx = (float)ix + fxv;
    float gy = (float)iy + fyv;
    float x0f = floorf(gx), y0f = floorf(gy);
    float wx1 = gx - x0f, wy1 = gy - y0f;
    float wx0 = 1.0f - wx1, wy0 = 1.0f - wy1;
    int x0 = (int)x0f, y0 = (int)y0f;
    bool vx0 = ((unsigned)x0 < (unsigned)W_);
    bool vx1 = ((unsigned)(x0 + 1) < (unsigned)W_);
    bool vy0 = ((unsigned)y0 < (unsigned)H_);
    bool vy1 = ((unsigned)(y0 + 1) < (unsigned)H_);
    float c00 = (vx0 && vy0) ? wx0 * wy0 : 0.0f;
    float c10 = (vx1 && vy0) ? wx1 * wy0 : 0.0f;
    float c01 = (vx0 && vy1) ? wx0 * wy1 : 0.0f;
    float c11 = (vx1 && vy1) ? wx1 * wy1 : 0.0f;
    float m = (c00 + c10) + (c01 + c11);
    float cx1 = c10 + c11;
    float cy1 = c01 + c11;
    float ox = fmaf(m, (float)x0, cx1) * INVW;
    float oy = fmaf(m, (float)y0, cy1) * INVH;
    float M = (m < 0.9999f) ? 0.0f : 1.0f;
    return make_float2(ox * M, oy * M);
}

// General (boundary) path given the 4 corner flow float2s.
__device__ __forceinline__ float slow_eval(
    float2 f00, float2 f10, float2 f01, float2 f11,
    int x0, int y0, float wx0, float wx1, float wy0, float wy1,
    float Gx, float Gy)
{
    int x1 = x0 + 1, y1 = y0 + 1;
    bool vx0 = ((unsigned)x0 < (unsigned)W_);
    bool vx1 = ((unsigned)x1 < (unsigned)W_);
    bool vy0 = ((unsigned)y0 < (unsigned)H_);
    bool vy1 = ((unsigned)y1 < (unsigned)H_);
    float w00 = (vx0 && vy0) ? wx0 * wy0 : 0.0f;
    float w10 = (vx1 && vy0) ? wx1 * wy0 : 0.0f;
    float w01 = (vx0 && vy1) ? wx0 * wy1 : 0.0f;
    float w11 = (vx1 && vy1) ? wx1 * wy1 : 0.0f;

    float2 v00 = m1_from(f00.x, f00.y, x0, y0);
    float2 v10 = m1_from(f10.x, f10.y, x1, y0);
    float2 v01 = m1_from(f01.x, f01.y, x0, y1);
    float2 v11 = m1_from(f11.x, f11.y, x1, y1);

    float mask = (w00 + w10) + (w01 + w11);
    float mx = fmaf(w00, v00.x, fmaf(w10, v10.x, fmaf(w01, v01.x, w11 * v11.x)));
    float my = fmaf(w00, v00.y, fmaf(w10, v10.y, fmaf(w01, v01.y, w11 * v11.y)));
    float M = (mask < 0.9999f) ? 0.0f : 1.0f;
    mx *= M; my *= M;
    float dx = Gx - mx, dy = Gy - my;
    return fast_sqrt(fmaf(dx, dx, fmaf(dy, dy, EPS2)));
}

// General per-pixel path (edge/dirty blocks): tile guard + interior test +
// boundary math + rare clamped-global fallback.
__device__ __forceinline__ float dir_diff(const __half2* __restrict__ t1,
                                          const float* __restrict__ g1x,
                                          const float* __restrict__ g1y,
                                          float f2x, float f2y,
                                          int px, int py, int tx0, int ty0,
                                          float Gx, float Gy)
{
    float sxf = (float)px + f2x;
    float syf = (float)py + f2y;
    float x0f = floorf(sxf), y0f = floorf(syf);
    float wx1 = sxf - x0f, wy1 = syf - y0f;
    float wx0 = 1.0f - wx1, wy0 = 1.0f - wy1;
    int x0 = (int)x0f, y0 = (int)y0f;

    int lx0 = x0 - tx0, ly0 = y0 - ty0;
    if (((unsigned)lx0 <= (unsigned)(TW - 2)) &
        ((unsigned)ly0 <= (unsigned)(TH - 2))) {
        int b = ly0 * TW + lx0;
        float2 f00 = __half22float2(t1[b]);
        float2 f10 = __half22float2(t1[b + 1]);
        float2 f01 = __half22float2(t1[b + TW]);
        float2 f11 = __half22float2(t1[b + TW + 1]);

        float x1f = x0f + 1.0f, y1f = y0f + 1.0f;
        float mnfx = fminf(fminf(f00.x, f01.x), fminf(f10.x, f11.x));
        float mxfx = fmaxf(fmaxf(f00.x, f01.x), fmaxf(f10.x, f11.x));
        float mnfy = fminf(fminf(f00.y, f01.y), fminf(f10.y, f11.y));
        float mxfy = fmaxf(fmaxf(f00.y, f01.y), fmaxf(f10.y, f11.y));
        bool inner = (sxf >= 0.0f) & (sxf <= WM1F) &
                     (syf >= 0.0f) & (syf <= HM1F) &
                     (x0f + mnfx >= 0.0f) & (x1f + mxfx <= WM1F) &
                     (y0f + mnfy >= 0.0f) & (y1f + mxfy <= HM1F);
        if (inner) {
            float ftx = fmaf(wx1, f10.x - f00.x, f00.x);
            float fbx = fmaf(wx1, f11.x - f01.x, f01.x);
            float bfx = fmaf(wy1, fbx - ftx, ftx);
            float fty = fmaf(wx1, f10.y - f00.y, f00.y);
            float fby = fmaf(wx1, f11.y - f01.y, f01.y);
            float bfy = fmaf(wy1, fby - fty, fty);
            float dx = (f2x + bfx) * INVW;
            float dy = (f2y + bfy) * INVH;
            return fast_sqrt(fmaf(dx, dx, fmaf(dy, dy, EPS2)));
        }
        return slow_eval(f00, f10, f01, f11, x0, y0, wx0, wx1, wy0, wy1, Gx, Gy);
    }
    {
        int x1 = x0 + 1, y1 = y0 + 1;
        int xc0 = min(max(x0, 0), W_ - 1);
        int xc1 = min(max(x1, 0), W_ - 1);
        int yc0 = min(max(y0, 0), H_ - 1);
        int yc1 = min(max(y1, 0), H_ - 1);
        int b00 = yc0 * W_ + xc0, b10 = yc0 * W_ + xc1;
        int b01 = yc1 * W_ + xc0, b11 = yc1 * W_ + xc1;
        float2 f00 = make_float2(__ldg(g1x + b00), __ldg(g1y + b00));
        float2 f10 = make_float2(__ldg(g1x + b10), __ldg(g1y + b10));
        float2 f01 = make_float2(__ldg(g1x + b01), __ldg(g1y + b01));
        float2 f11 = make_float2(__ldg(g1x + b11), __ldg(g1y + b11));
        return slow_eval(f00, f10, f01, f11, x0, y0, wx0, wx1, wy0, wy1, Gx, Gy);
    }
}

// Clean-block fast path: unconditional telescoped form, bilerp in half2.
__device__ __forceinline__ float dir_fast(const __half2* __restrict__ t1,
                                          float f2x, float f2y,
                                          int px, int py, int tx0, int ty0)
{
    const __half2 ONE = __float2half2_rn(1.0f);
    float sxf = (float)px + f2x;
    float syf = (float)py + f2y;
    float x0f = floorf(sxf), y0f = floorf(syf);
    float wx1 = sxf - x0f, wy1 = syf - y0f;
    int b = ((int)y0f - ty0) * TW + ((int)x0f - tx0);

    __half2 f00 = t1[b];
    __half2 f10 = t1[b + 1];
    __half2 f01 = t1[b + TW];
    __half2 f11 = t1[b + TW + 1];

    __half2 hx1 = __float2half2_rn(wx1);
    __half2 hy1 = __float2half2_rn(wy1);
    __half2 hx0 = __hsub2(ONE, hx1);
    __half2 hy0 = __hsub2(ONE, hy1);

    __half2 top = __hfma2(f10, hx1, __hmul2(f00, hx0));
    __half2 bot = __hfma2(f11, hx1, __hmul2(f01, hx0));
    __half2 r   = __hfma2(bot, hy1, __hmul2(top, hy0));
    float2 bf = __half22float2(r);

    float dx = (f2x + bf.x) * INVW;
    float dy = (f2y + bf.y) * INVH;
    return fast_sqrt(fmaf(dx, dx, fmaf(dy, dy, EPS2)));
}

__device__ __forceinline__ unsigned h2u(__half2 h)
{
    return *reinterpret_cast<unsigned*>(&h);
}

__global__ __launch_bounds__(NT, 4)
void fused_cycle_kernel(const float* __restrict__ A, const float* __restrict__ B,
                        float* __restrict__ out)
{
    __shared__ __half2 tA[TSZ];
    __shared__ __half2 tB[TSZ];

    int n = blockIdx.z;
    const float* Ax = A + (size_t)n * 2 * HW_;
    const float* Ay = Ax + HW_;
    const float* Bx = B + (size_t)n * 2 * HW_;
    const float* By = Bx + HW_;

    int tx0 = blockIdx.x * BX - R_;
    int ty0 = blockIdx.y * RPB - R_;
    int tid = threadIdx.y * BX + threadIdx.x;

    bool edgeBlk = (blockIdx.x < 1) | (blockIdx.x > GX_ - 2) |
                   (blockIdx.y < 1) | (blockIdx.y > GY_ - 2);
    int dirty = edgeBlk ? 1 : 0;

    // Tile fill: tile cell == clamped-global value, quantized to half2.
    if (blockIdx.x >= 1 && blockIdx.x <= GX_ - 2) {
        for (int i = tid; i < NV4; i += NT) {
            int ly = i / (TW / 4);
            int lxg = (i - ly * (TW / 4)) * 4;
            int gy = min(max(ty0 + ly, 0), H_ - 1);
            int idx = gy * W_ + tx0 + lxg;
            float4 ax = *(const float4*)(Ax + idx);
            float4 ay = *(const float4*)(Ay + idx);
            float4 bx = *(const float4*)(Bx + idx);
            float4 by = *(const float4*)(By + idx);
            float ma = fmaxf(fmaxf(fmaxf(fabsf(ax.x), fabsf(ax.y)),
                                   fmaxf(fabsf(ax.z), fabsf(ax.w))),
                             fmaxf(fmaxf(fabsf(ay.x), fabsf(ay.y)),
                                   fmaxf(fabsf(ay.z), fabsf(ay.w))));
            float mb = fmaxf(fmaxf(fmaxf(fabsf(bx.x), fabsf(bx.y)),
                                   fmaxf(fabsf(bx.z), fabsf(bx.w))),
                             fmaxf(fmaxf(fabsf(by.x), fabsf(by.y)),
                                   fmaxf(fabsf(by.z), fabsf(by.w))));
            if (fmaxf(ma, mb) >= CLEAN_TH) dirty = 1;
            int c = ly * TW + lxg;
            uint4 va = make_uint4(h2u(__floats2half2_rn(ax.x, ay.x)),
                                  h2u(__floats2half2_rn(ax.y, ay.y)),
                                  h2u(__floats2half2_rn(ax.z, ay.z)),
                                  h2u(__floats2half2_rn(ax.w, ay.w)));
            uint4 vb = make_uint4(h2u(__floats2half2_rn(bx.x, by.x)),
                                  h2u(__floats2half2_rn(bx.y, by.y)),
                                  h2u(__floats2half2_rn(bx.z, by.z)),
                                  h2u(__floats2half2_rn(bx.w, by.w)));
            *(uint4*)&tA[c] = va;
            *(uint4*)&tB[c] = vb;
        }
    } else {
        for (int i = tid; i < TSZ; i += NT) {
            int ly = i / TW, lx = i - ly * TW;
            int gx = min(max(tx0 + lx, 0), W_ - 1);
            int gy = min(max(ty0 + ly, 0), H_ - 1);
            int idx = gy * W_ + gx;
            tA[i] = __floats2half2_rn(__ldg(Ax + idx), __ldg(Ay + idx));
            tB[i] = __floats2half2_rn(__ldg(Bx + idx), __ldg(By + idx));
        }
    }

    int px = blockIdx.x * BX + threadIdx.x;
    int py0 = blockIdx.y * RPB + threadIdx.y;        // row 0
    int py1 = py0 + BY;                              // row 1 (16 apart)
    int idx0 = py0 * W_ + px;
    int idx1 = py1 * W_ + px;
    float aox0 = __ldg(Ax + idx0), aoy0 = __ldg(Ay + idx0);
    float box0 = __ldg(Bx + idx0), boy0 = __ldg(By + idx0);
    float aox1 = __ldg(Ax + idx1), aoy1 = __ldg(Ay + idx1);
    float box1 = __ldg(Bx + idx1), boy1 = __ldg(By + idx1);

    bool fastBlk = (__syncthreads_or(dirty) == 0);   // also the fill barrier

    float s;
    if (fastBlk) {
        s = dir_fast(tA, box0, boy0, px, py0, tx0, ty0)
          + dir_fast(tB, aox0, aoy0, px, py0, tx0, ty0)
          + dir_fast(tA, box1, boy1, px, py1, tx0, ty0)
          + dir_fast(tB, aox1, aoy1, px, py1, tx0, ty0);
    } else {
        float Gx  = (float)px  * INVW;
        float Gy0 = (float)py0 * INVH;
        float Gy1 = (float)py1 * INVH;
        s = dir_diff(tA, Ax, Ay, box0, boy0, px, py0, tx0, ty0, Gx, Gy0)
          + dir_diff(tB, Bx, By, aox0, aoy0, px, py0, tx0, ty0, Gx, Gy0)
          + dir_diff(tA, Ax, Ay, box1, boy1, px, py1, tx0, ty0, Gx, Gy1)
          + dir_diff(tB, Bx, By, aox1, aoy1, px, py1, tx0, ty0, Gx, Gy1);
    }

    // Block reduction (16 warps)
    #pragma unroll
    for (int o = 16; o > 0; o >>= 1)
        s += __shfl_down_sync(0xffffffffu, s, o);
    __shared__ float shred[NT / 32];
    if ((tid & 31) == 0) shred[tid >> 5] = s;
    __syncthreads();
    if (tid < 16) {
        float v = shred[tid];
        #pragma unroll
        for (int o = 8; o > 0; o >>= 1)
            v += __shfl_down_sync(0x0000ffffu, v, o);
        if (tid == 0) {
            int bid = blockIdx.x + GX_ * (blockIdx.y + GY_ * blockIdx.z);
            g_partials[bid] = v;
        }
    }

    // Last-block-standing fused final reduce (deterministic).
    __shared__ bool amLast;
    __threadfence();
    if (tid == 0) {
        unsigned long long old = atomicAdd(&g_ticket, 1ULL);
        amLast = ((old % (unsigned long long)NBLK) == (unsigned long long)(NBLK - 1));
    }
    __syncthreads();
    if (amLast) {
        const float4* p4 = (const float4*)g_partials;  // NBLK % 4 == 0
        const int n4 = NBLK / 4;                       // 2304
        double acc = 0.0;
        for (int i = tid; i < n4; i += NT) {
            float4 v = __ldcg(p4 + i);
            acc += (double)((v.x + v.y) + (v.z + v.w));
        }
        #pragma unroll
        for (int o = 16; o > 0; o >>= 1)
            acc += __shfl_down_sync(0xffffffffu, acc, o);
        __shared__ double shd[NT / 32];
        if ((tid & 31) == 0) shd[tid >> 5] = acc;
        __syncthreads();
        if (tid < 16) {
            double v = shd[tid];
            #pragma unroll
            for (int o = 8; o > 0; o >>= 1)
                v += __shfl_down_sync(0x0000ffffu, v, o);
            if (tid == 0)
                out[0] = (float)(v / ((double)N_ * (double)HW_));
        }
    }
}

extern "C" void kernel_launch(void* const* d_in, const int* in_sizes, int n_in,
                              void* d_out, int out_size)
{
    const float* A = (const float*)d_in[0];  // UV_AtoB
    const float* B = (const float*)d_in[1];  // UV_BtoA
    dim3 block(BX, BY);
    dim3 grid(GX_, GY_, N_);
    fused_cycle_kernel<<<grid, block>>>(A, B, (float*)d_out);
}

// round 11
// speedup vs baseline: 2.4162x; 1.0358x over previous
#include <cuda_runtime.h>
#include <cuda_fp16.h>

#define W_ 768
#define H_ 768
#define N_ 16
#define HW_ (H_ * W_)
#define BX 32
#define BY 16
#define NT (BX * BY)           /* 512 */
#define RPB 64                 /* pixel rows per block (4 per thread) */
#define R_ 8
#define TW 52                  /* padded tile width (mult of 4) */
#define TH (RPB + 2 * R_ + 1)  /* 81 */
#define TSZ (TW * TH)          /* 4212 half2 cells */
#define NV4 (TSZ / 4)          /* 1053 */
#define GX_ (W_ / BX)          /* 24 */
#define GY_ (H_ / RPB)         /* 12 */
#define NBLK (GX_ * GY_ * N_)  /* 4608 */
#define EPS2 1.0e-6f
#define INVW (1.0f / 767.0f)
#define INVH (1.0f / 767.0f)
#define WM1F 767.0f
#define HM1F 767.0f
#define CLEAN_TH 6.98f

__device__ float g_partials[NBLK];
__device__ unsigned long long g_ticket;  // monotonic across graph replays

__device__ __forceinline__ float fast_sqrt(float v)
{
    return v * __frsqrt_rn(v);   // v >= EPS2 > 0 always
}

// General m1 = warp(GridXY, flo1) at integer pixel (ix,iy): closed form.
__device__ __forceinline__ float2 m1_from(float fxv, float fyv, int ix, int iy)
{
    float gx = (float)ix + fxv;
    float gy = (float)iy + fyv;
    float x0f = floorf(gx), y0f = floorf(gy);
    float wx1 = gx - x0f, wy1 = gy - y0f;
    float wx0 = 1.0f - wx1, wy0 = 1.0f - wy1;
    int x0 = (int)x0f, y0 = (int)y0f;
    bool vx0 = ((unsigned)x0 < (unsigned)W_);
    bool vx1 = ((unsigned)(x0 + 1) < (unsigned)W_);
    bool vy0 = ((unsigned)y0 < (unsigned)H_);
    bool vy1 = ((unsigned)(y0 + 1) < (unsigned)H_);
    float c00 = (vx0 && vy0) ? wx0 * wy0 : 0.0f;
    float c10 = (vx1 && vy0) ? wx1 * wy0 : 0.0f;
    float c01 = (vx0 && vy1) ? wx0 * wy1 : 0.0f;
    float c11 = (vx1 && vy1) ? wx1 * wy1 : 0.0f;
    float m = (c00 + c10) + (c01 + c11);
    float cx1 = c10 + c11;
    float cy1 = c01 + c11;
    float ox = fmaf(m, (float)x0, cx1) * INVW;
    float oy = fmaf(m, (float)y0, cy1) * INVH;
    float M = (m < 0.9999f) ? 0.0f : 1.0f;
    return make_float2(ox * M, oy * M);
}

__device__ __forceinline__ float slow_eval(
    float2 f00, float2 f10, float2 f01, float2 f11,
    int x0, int y0, float wx0, float wx1, float wy0, float wy1,
    float Gx, float Gy)
{
    int x1 = x0 + 1, y1 = y0 + 1;
    bool vx0 = ((unsigned)x0 < (unsigned)W_);
    bool vx1 = ((unsigned)x1 < (unsigned)W_);
    bool vy0 = ((unsigned)y0 < (unsigned)H_);
    bool vy1 = ((unsigned)y1 < (unsigned)H_);
    float w00 = (vx0 && vy0) ? wx0 * wy0 : 0.0f;
    float w10 = (vx1 && vy0) ? wx1 * wy0 : 0.0f;
    float w01 = (vx0 && vy1) ? wx0 * wy1 : 0.0f;
    float w11 = (vx1 && vy1) ? wx1 * wy1 : 0.0f;

    float2 v00 = m1_from(f00.x, f00.y, x0, y0);
    float2 v10 = m1_from(f10.x, f10.y, x1, y0);
    float2 v01 = m1_from(f01.x, f01.y, x0, y1);
    float2 v11 = m1_from(f11.x, f11.y, x1, y1);

    float mask = (w00 + w10) + (w01 + w11);
    float mx = fmaf(w00, v00.x, fmaf(w10, v10.x, fmaf(w01, v01.x, w11 * v11.x)));
    float my = fmaf(w00, v00.y, fmaf(w10, v10.y, fmaf(w01, v01.y, w11 * v11.y)));
    float M = (mask < 0.9999f) ? 0.0f : 1.0f;
    mx *= M; my *= M;
    float dx = Gx - mx, dy = Gy - my;
    return fast_sqrt(fmaf(dx, dx, fmaf(dy, dy, EPS2)));
}

// General per-pixel path (margin/dirty pixels): tile guard + interior test +
// boundary math + rare clamped-global fallback. f2 is fp32 (from global).
__device__ __forceinline__ float dir_diff(const __half2* __restrict__ t1,
                                          const float* __restrict__ g1x,
                                          const float* __restrict__ g1y,
                                          float f2x, float f2y,
                                          int px, int py, int tx0, int ty0,
                                          float Gx, float Gy)
{
    float sxf = (float)px + f2x;
    float syf = (float)py + f2y;
    float x0f = floorf(sxf), y0f = floorf(syf);
    float wx1 = sxf - x0f, wy1 = syf - y0f;
    float wx0 = 1.0f - wx1, wy0 = 1.0f - wy1;
    int x0 = (int)x0f, y0 = (int)y0f;

    int lx0 = x0 - tx0, ly0 = y0 - ty0;
    if (((unsigned)lx0 <= (unsigned)(TW - 2)) &
        ((unsigned)ly0 <= (unsigned)(TH - 2))) {
        int b = ly0 * TW + lx0;
        float2 f00 = __half22float2(t1[b]);
        float2 f10 = __half22float2(t1[b + 1]);
        float2 f01 = __half22float2(t1[b + TW]);
        float2 f11 = __half22float2(t1[b + TW + 1]);

        float x1f = x0f + 1.0f, y1f = y0f + 1.0f;
        float mnfx = fminf(fminf(f00.x, f01.x), fminf(f10.x, f11.x));
        float mxfx = fmaxf(fmaxf(f00.x, f01.x), fmaxf(f10.x, f11.x));
        float mnfy = fminf(fminf(f00.y, f01.y), fminf(f10.y, f11.y));
        float mxfy = fmaxf(fmaxf(f00.y, f01.y), fmaxf(f10.y, f11.y));
        bool inner = (sxf >= 0.0f) & (sxf <= WM1F) &
                     (syf >= 0.0f) & (syf <= HM1F) &
                     (x0f + mnfx >= 0.0f) & (x1f + mxfx <= WM1F) &
                     (y0f + mnfy >= 0.0f) & (y1f + mxfy <= HM1F);
        if (inner) {
            float ftx = fmaf(wx1, f10.x - f00.x, f00.x);
            float fbx = fmaf(wx1, f11.x - f01.x, f01.x);
            float bfx = fmaf(wy1, fbx - ftx, ftx);
            float fty = fmaf(wx1, f10.y - f00.y, f00.y);
            float fby = fmaf(wx1, f11.y - f01.y, f01.y);
            float bfy = fmaf(wy1, fby - fty, fty);
            float dx = (f2x + bfx) * INVW;
            float dy = (f2y + bfy) * INVH;
            return fast_sqrt(fmaf(dx, dx, fmaf(dy, dy, EPS2)));
        }
        return slow_eval(f00, f10, f01, f11, x0, y0, wx0, wx1, wy0, wy1, Gx, Gy);
    }
    {
        int x1 = x0 + 1, y1 = y0 + 1;
        int xc0 = min(max(x0, 0), W_ - 1);
        int xc1 = min(max(x1, 0), W_ - 1);
        int yc0 = min(max(y0, 0), H_ - 1);
        int yc1 = min(max(y1, 0), H_ - 1);
        int b00 = yc0 * W_ + xc0, b10 = yc0 * W_ + xc1;
        int b01 = yc1 * W_ + xc0, b11 = yc1 * W_ + xc1;
        float2 f00 = make_float2(__ldg(g1x + b00), __ldg(g1y + b00));
        float2 f10 = make_float2(__ldg(g1x + b10), __ldg(g1y + b10));
        float2 f01 = make_float2(__ldg(g1x + b01), __ldg(g1y + b01));
        float2 f11 = make_float2(__ldg(g1x + b11), __ldg(g1y + b11));
        return slow_eval(f00, f10, f01, f11, x0, y0, wx0, wx1, wy0, wy1, Gx, Gy);
    }
}

// Fast path: clean data + pixel in [14,751]^2 margin -> all masks provably 1,
// telescoped form; bilerp in half2; f2 taken from tile (quantized).
__device__ __forceinline__ float dir_fast(const __half2* __restrict__ t1,
                                          float f2x, float f2y,
                                          int px, int py, int tx0, int ty0)
{
    const __half2 ONE = __float2half2_rn(1.0f);
    float sxf = (float)px + f2x;
    float syf = (float)py + f2y;
    float x0f = floorf(sxf), y0f = floorf(syf);
    float wx1 = sxf - x0f, wy1 = syf - y0f;
    int b = ((int)y0f - ty0) * TW + ((int)x0f - tx0);

    __half2 f00 = t1[b];
    __half2 f10 = t1[b + 1];
    __half2 f01 = t1[b + TW];
    __half2 f11 = t1[b + TW + 1];

    __half2 hx1 = __float2half2_rn(wx1);
    __half2 hy1 = __float2half2_rn(wy1);
    __half2 hx0 = __hsub2(ONE, hx1);
    __half2 hy0 = __hsub2(ONE, hy1);

    __half2 top = __hfma2(f10, hx1, __hmul2(f00, hx0));
    __half2 bot = __hfma2(f11, hx1, __hmul2(f01, hx0));
    __half2 r   = __hfma2(bot, hy1, __hmul2(top, hy0));
    float2 bf = __half22float2(r);

    float dx = (f2x + bf.x) * INVW;
    float dy = (f2y + bf.y) * INVH;
    return fast_sqrt(fmaf(dx, dx, fmaf(dy, dy, EPS2)));
}

__device__ __forceinline__ unsigned h2u(__half2 h)
{
    return *reinterpret_cast<unsigned*>(&h);
}

__global__ __launch_bounds__(NT, 4)
void fused_cycle_kernel(const float* __restrict__ A, const float* __restrict__ B,
                        float* __restrict__ out)
{
    __shared__ __half2 tA[TSZ];
    __shared__ __half2 tB[TSZ];

    int n = blockIdx.z;
    const float* Ax = A + (size_t)n * 2 * HW_;
    const float* Ay = Ax + HW_;
    const float* Bx = B + (size_t)n * 2 * HW_;
    const float* By = Bx + HW_;

    int tx0 = blockIdx.x * BX - R_;
    int ty0 = blockIdx.y * RPB - R_;
    int tid = threadIdx.y * BX + threadIdx.x;

    int dirty = 0;

    // Tile fill: tile cell == clamped-global value, quantized to half2.
    if (blockIdx.x >= 1 && blockIdx.x <= GX_ - 2) {
        for (int i = tid; i < NV4; i += NT) {
            int ly = i / (TW / 4);
            int lxg = (i - ly * (TW / 4)) * 4;
            int gy = min(max(ty0 + ly, 0), H_ - 1);
            int idx = gy * W_ + tx0 + lxg;
            float4 ax = *(const float4*)(Ax + idx);
            float4 ay = *(const float4*)(Ay + idx);
            float4 bx = *(const float4*)(Bx + idx);
            float4 by = *(const float4*)(By + idx);
            float ma = fmaxf(fmaxf(fmaxf(fabsf(ax.x), fabsf(ax.y)),
                                   fmaxf(fabsf(ax.z), fabsf(ax.w))),
                             fmaxf(fmaxf(fabsf(ay.x), fabsf(ay.y)),
                                   fmaxf(fabsf(ay.z), fabsf(ay.w))));
            float mb = fmaxf(fmaxf(fmaxf(fabsf(bx.x), fabsf(bx.y)),
                                   fmaxf(fabsf(bx.z), fabsf(bx.w))),
                             fmaxf(fmaxf(fabsf(by.x), fabsf(by.y)),
                                   fmaxf(fabsf(by.z), fabsf(by.w))));
            if (fmaxf(ma, mb) >= CLEAN_TH) dirty = 1;
            int c = ly * TW + lxg;
            uint4 va = make_uint4(h2u(__floats2half2_rn(ax.x, ay.x)),
                                  h2u(__floats2half2_rn(ax.y, ay.y)),
                                  h2u(__floats2half2_rn(ax.z, ay.z)),
                                  h2u(__floats2half2_rn(ax.w, ay.w)));
            uint4 vb = make_uint4(h2u(__floats2half2_rn(bx.x, by.x)),
                                  h2u(__floats2half2_rn(bx.y, by.y)),
                                  h2u(__floats2half2_rn(bx.z, by.z)),
                                  h2u(__floats2half2_rn(bx.w, by.w)));
            *(uint4*)&tA[c] = va;
            *(uint4*)&tB[c] = vb;
        }
    } else {
        for (int i = tid; i < TSZ; i += NT) {
            int ly = i / TW, lx = i - ly * TW;
            int gx = min(max(tx0 + lx, 0), W_ - 1);
            int gy = min(max(ty0 + ly, 0), H_ - 1);
            int idx = gy * W_ + gx;
            float fax = __ldg(Ax + idx), fay = __ldg(Ay + idx);
            float fbx = __ldg(Bx + idx), fby = __ldg(By + idx);
            if (fmaxf(fmaxf(fabsf(fax), fabsf(fay)),
                      fmaxf(fabsf(fbx), fabsf(fby))) >= CLEAN_TH) dirty = 1;
            tA[i] = __floats2half2_rn(fax, fay);
            tB[i] = __floats2half2_rn(fbx, fby);
        }
    }

    bool dataClean = (__syncthreads_or(dirty) == 0);  // also the fill barrier

    int px = blockIdx.x * BX + threadIdx.x;
    int py0 = blockIdx.y * RPB + threadIdx.y;
    bool pxIn = ((unsigned)(px - 14) <= 737u);

    float s = 0.0f;
    #pragma unroll
    for (int r = 0; r < 4; r++) {
        int py = py0 + r * BY;
        bool fast = dataClean & pxIn & ((unsigned)(py - 14) <= 737u);
        if (fast) {
            int lown = (py - ty0) * TW + (threadIdx.x + R_);
            float2 bo = __half22float2(tB[lown]);
            float2 ao = __half22float2(tA[lown]);
            s += dir_fast(tA, bo.x, bo.y, px, py, tx0, ty0)
               + dir_fast(tB, ao.x, ao.y, px, py, tx0, ty0);
        } else {
            int idx = py * W_ + px;
            float aox = __ldg(Ax + idx), aoy = __ldg(Ay + idx);
            float box = __ldg(Bx + idx), boy = __ldg(By + idx);
            float Gx = (float)px * INVW;
            float Gy = (float)py * INVH;
            s += dir_diff(tA, Ax, Ay, box, boy, px, py, tx0, ty0, Gx, Gy)
               + dir_diff(tB, Bx, By, aox, aoy, px, py, tx0, ty0, Gx, Gy);
        }
    }

    // Block reduction (16 warps)
    #pragma unroll
    for (int o = 16; o > 0; o >>= 1)
        s += __shfl_down_sync(0xffffffffu, s, o);
    __shared__ float shred[NT / 32];
    if ((tid & 31) == 0) shred[tid >> 5] = s;
    __syncthreads();
    if (tid < 16) {
        float v = shred[tid];
        #pragma unroll
        for (int o = 8; o > 0; o >>= 1)
            v += __shfl_down_sync(0x0000ffffu, v, o);
        if (tid == 0) {
            int bid = blockIdx.x + GX_ * (blockIdx.y + GY_ * blockIdx.z);
            g_partials[bid] = v;
        }
    }

    // Last-block-standing fused final reduce (deterministic).
    __shared__ bool amLast;
    __threadfence();
    if (tid == 0) {
        unsigned long long old = atomicAdd(&g_ticket, 1ULL);
        amLast = ((old % (unsigned long long)NBLK) == (unsigned long long)(NBLK - 1));
    }
    __syncthreads();
    if (amLast) {
        const float4* p4 = (const float4*)g_partials;  // NBLK % 4 == 0
        const int n4 = NBLK / 4;                       // 1152
        double acc = 0.0;
        for (int i = tid; i < n4; i += NT) {
            float4 v = __ldcg(p4 + i);
            acc += (double)((v.x + v.y) + (v.z + v.w));
        }
        #pragma unroll
        for (int o = 16; o > 0; o >>= 1)
            acc += __shfl_down_sync(0xffffffffu, acc, o);
        __shared__ double shd[NT / 32];
        if ((tid & 31) == 0) shd[tid >> 5] = acc;
        __syncthreads();
        if (tid < 16) {
            double v = shd[tid];
            #pragma unroll
            for (int o = 8; o > 0; o >>= 1)
                v += __shfl_down_sync(0x0000ffffu, v, o);
            if (tid == 0)
                out[0] = (float)(v / ((double)N_ * (double)HW_));
        }
    }
}

extern "C" void kernel_launch(void* const* d_in, const int* in_sizes, int n_in,
                              void* d_out, int out_size)
{
    const float* A = (const float*)d_in[0];  // UV_AtoB
    const float* B = (const float*)d_in[1];  // UV_BtoA
    dim3 block(BX, BY);
    dim3 grid(GX_, GY_, N_);
    fused_cycle_kernel<<<grid, block>>>(A, B, (float*)d_out);
}

// round 12
// speedup vs baseline: 2.5155x; 1.0411x over previous
#include <cuda_runtime.h>
#include <cuda_fp16.h>

#define W_ 768
#define H_ 768
#define N_ 16
#define HW_ (H_ * W_)
#define BX 32
#define BY 16
#define NT (BX * BY)           /* 512 */
#define RPB 64                 /* pixel rows per block (4 per thread) */
#define R_ 8
#define TW 52                  /* padded tile width (mult of 4) */
#define TH (RPB + 2 * R_ + 1)  /* 81 */
#define TSZ (TW * TH)          /* 4212 half2 cells */
#define NV4 (TSZ / 4)          /* 1053 */
#define GX_ (W_ / BX)          /* 24 */
#define GY_ (H_ / RPB)         /* 12 */
#define NBLK (GX_ * GY_ * N_)  /* 4608 */
#define EPS2 1.0e-6f
#define INVW (1.0f / 767.0f)
#define INVH (1.0f / 767.0f)
#define WM1F 767.0f
#define HM1F 767.0f
#define CLEAN_TH_H 6.95f       /* conservative vs half rounding of 6.98 */
#define CLEAN_TH_F 6.98f

__device__ float g_partials[NBLK];
__device__ unsigned long long g_ticket;  // monotonic across graph replays

__device__ __forceinline__ float fast_sqrt(float v)
{
    return v * __frsqrt_rn(v);   // v >= EPS2 > 0 always
}

// General m1 = warp(GridXY, flo1) at integer pixel (ix,iy): closed form.
__device__ __forceinline__ float2 m1_from(float fxv, float fyv, int ix, int iy)
{
    float gx = (float)ix + fxv;
    float gy = (float)iy + fyv;
    float x0f = floorf(gx), y0f = floorf(gy);
    float wx1 = gx - x0f, wy1 = gy - y0f;
    float wx0 = 1.0f - wx1, wy0 = 1.0f - wy1;
    int x0 = (int)x0f, y0 = (int)y0f;
    bool vx0 = ((unsigned)x0 < (unsigned)W_);
    bool vx1 = ((unsigned)(x0 + 1) < (unsigned)W_);
    bool vy0 = ((unsigned)y0 < (unsigned)H_);
    bool vy1 = ((unsigned)(y0 + 1) < (unsigned)H_);
    float c00 = (vx0 && vy0) ? wx0 * wy0 : 0.0f;
    float c10 = (vx1 && vy0) ? wx1 * wy0 : 0.0f;
    float c01 = (vx0 && vy1) ? wx0 * wy1 : 0.0f;
    float c11 = (vx1 && vy1) ? wx1 * wy1 : 0.0f;
    float m = (c00 + c10) + (c01 + c11);
    float cx1 = c10 + c11;
    float cy1 = c01 + c11;
    float ox = fmaf(m, (float)x0, cx1) * INVW;
    float oy = fmaf(m, (float)y0, cy1) * INVH;
    float M = (m < 0.9999f) ? 0.0f : 1.0f;
    return make_float2(ox * M, oy * M);
}

__device__ __forceinline__ float slow_eval(
    float2 f00, float2 f10, float2 f01, float2 f11,
    int x0, int y0, float wx0, float wx1, float wy0, float wy1,
    float Gx, float Gy)
{
    int x1 = x0 + 1, y1 = y0 + 1;
    bool vx0 = ((unsigned)x0 < (unsigned)W_);
    bool vx1 = ((unsigned)x1 < (unsigned)W_);
    bool vy0 = ((unsigned)y0 < (unsigned)H_);
    bool vy1 = ((unsigned)y1 < (unsigned)H_);
    float w00 = (vx0 && vy0) ? wx0 * wy0 : 0.0f;
    float w10 = (vx1 && vy0) ? wx1 * wy0 : 0.0f;
    float w01 = (vx0 && vy1) ? wx0 * wy1 : 0.0f;
    float w11 = (vx1 && vy1) ? wx1 * wy1 : 0.0f;

    float2 v00 = m1_from(f00.x, f00.y, x0, y0);
    float2 v10 = m1_from(f10.x, f10.y, x1, y0);
    float2 v01 = m1_from(f01.x, f01.y, x0, y1);
    float2 v11 = m1_from(f11.x, f11.y, x1, y1);

    float mask = (w00 + w10) + (w01 + w11);
    float mx = fmaf(w00, v00.x, fmaf(w10, v10.x, fmaf(w01, v01.x, w11 * v11.x)));
    float my = fmaf(w00, v00.y, fmaf(w10, v10.y, fmaf(w01, v01.y, w11 * v11.y)));
    float M = (mask < 0.9999f) ? 0.0f : 1.0f;
    mx *= M; my *= M;
    float dx = Gx - mx, dy = Gy - my;
    return fast_sqrt(fmaf(dx, dx, fmaf(dy, dy, EPS2)));
}

// General per-pixel path (margin/dirty pixels): tile guard + interior test +
// boundary math + rare clamped-global fallback. f2 is fp32 (from global).
__device__ __forceinline__ float dir_diff(const __half2* __restrict__ t1,
                                          const float* __restrict__ g1x,
                                          const float* __restrict__ g1y,
                                          float f2x, float f2y,
                                          int px, int py, int tx0, int ty0,
                                          float Gx, float Gy)
{
    float sxf = (float)px + f2x;
    float syf = (float)py + f2y;
    float x0f = floorf(sxf), y0f = floorf(syf);
    float wx1 = sxf - x0f, wy1 = syf - y0f;
    float wx0 = 1.0f - wx1, wy0 = 1.0f - wy1;
    int x0 = (int)x0f, y0 = (int)y0f;

    int lx0 = x0 - tx0, ly0 = y0 - ty0;
    if (((unsigned)lx0 <= (unsigned)(TW - 2)) &
        ((unsigned)ly0 <= (unsigned)(TH - 2))) {
        int b = ly0 * TW + lx0;
        float2 f00 = __half22float2(t1[b]);
        float2 f10 = __half22float2(t1[b + 1]);
        float2 f01 = __half22float2(t1[b + TW]);
        float2 f11 = __half22float2(t1[b + TW + 1]);

        float x1f = x0f + 1.0f, y1f = y0f + 1.0f;
        float mnfx = fminf(fminf(f00.x, f01.x), fminf(f10.x, f11.x));
        float mxfx = fmaxf(fmaxf(f00.x, f01.x), fmaxf(f10.x, f11.x));
        float mnfy = fminf(fminf(f00.y, f01.y), fminf(f10.y, f11.y));
        float mxfy = fmaxf(fmaxf(f00.y, f01.y), fmaxf(f10.y, f11.y));
        bool inner = (sxf >= 0.0f) & (sxf <= WM1F) &
                     (syf >= 0.0f) & (syf <= HM1F) &
                     (x0f + mnfx >= 0.0f) & (x1f + mxfx <= WM1F) &
                     (y0f + mnfy >= 0.0f) & (y1f + mxfy <= HM1F);
        if (inner) {
            float ftx = fmaf(wx1, f10.x - f00.x, f00.x);
            float fbx = fmaf(wx1, f11.x - f01.x, f01.x);
            float bfx = fmaf(wy1, fbx - ftx, ftx);
            float fty = fmaf(wx1, f10.y - f00.y, f00.y);
            float fby = fmaf(wx1, f11.y - f01.y, f01.y);
            float bfy = fmaf(wy1, fby - fty, fty);
            float dx = (f2x + bfx) * INVW;
            float dy = (f2y + bfy) * INVH;
            return fast_sqrt(fmaf(dx, dx, fmaf(dy, dy, EPS2)));
        }
        return slow_eval(f00, f10, f01, f11, x0, y0, wx0, wx1, wy0, wy1, Gx, Gy);
    }
    {
        int x1 = x0 + 1, y1 = y0 + 1;
        int xc0 = min(max(x0, 0), W_ - 1);
        int xc1 = min(max(x1, 0), W_ - 1);
        int yc0 = min(max(y0, 0), H_ - 1);
        int yc1 = min(max(y1, 0), H_ - 1);
        int b00 = yc0 * W_ + xc0, b10 = yc0 * W_ + xc1;
        int b01 = yc1 * W_ + xc0, b11 = yc1 * W_ + xc1;
        float2 f00 = make_float2(__ldg(g1x + b00), __ldg(g1y + b00));
        float2 f10 = make_float2(__ldg(g1x + b10), __ldg(g1y + b10));
        float2 f01 = make_float2(__ldg(g1x + b01), __ldg(g1y + b01));
        float2 f11 = make_float2(__ldg(g1x + b11), __ldg(g1y + b11));
        return slow_eval(f00, f10, f01, f11, x0, y0, wx0, wx1, wy0, wy1, Gx, Gy);
    }
}

// Fast path: tile-relative coords (u,v > 0 so trunc == floor), lerp-form
// half2 bilerp. ub = (px - tx0) as float, vb = (py - ty0) as float.
__device__ __forceinline__ float dir_fast(const __half2* __restrict__ t1,
                                          float f2x, float f2y,
                                          float ub, float vb)
{
    float u = ub + f2x;                  // in (1, TW-2): positive
    float v = vb + f2y;
    int iu = (int)u;                     // trunc == floor (u > 0)
    int iv = (int)v;
    float wx1 = u - (float)iu;
    float wy1 = v - (float)iv;
    int b = iv * TW + iu;

    __half2 f00 = t1[b];
    __half2 f10 = t1[b + 1];
    __half2 f01 = t1[b + TW];
    __half2 f11 = t1[b + TW + 1];

    __half2 hx1 = __float2half2_rn(wx1);
    __half2 hy1 = __float2half2_rn(wy1);

    __half2 top = __hfma2(__hsub2(f10, f00), hx1, f00);
    __half2 bot = __hfma2(__hsub2(f11, f01), hx1, f01);
    __half2 r   = __hfma2(__hsub2(bot, top), hy1, top);
    float2 bf = __half22float2(r);

    float dx = (f2x + bf.x) * INVW;
    float dy = (f2y + bf.y) * INVH;
    return fast_sqrt(fmaf(dx, dx, fmaf(dy, dy, EPS2)));
}

__device__ __forceinline__ unsigned h2u(__half2 h)
{
    return *reinterpret_cast<unsigned*>(&h);
}

__device__ __forceinline__ __half2 u2h(unsigned u)
{
    return *reinterpret_cast<__half2*>(&u);
}

__global__ __launch_bounds__(NT, 4)
void fused_cycle_kernel(const float* __restrict__ A, const float* __restrict__ B,
                        float* __restrict__ out)
{
    __shared__ __half2 tA[TSZ];
    __shared__ __half2 tB[TSZ];

    int n = blockIdx.z;
    const float* Ax = A + (size_t)n * 2 * HW_;
    const float* Ay = Ax + HW_;
    const float* Bx = B + (size_t)n * 2 * HW_;
    const float* By = Bx + HW_;

    int tx0 = blockIdx.x * BX - R_;
    int ty0 = blockIdx.y * RPB - R_;
    int tid = threadIdx.y * BX + threadIdx.x;

    int dirty = 0;

    // Tile fill: tile cell == clamped-global value, quantized to half2.
    if (blockIdx.x >= 1 && blockIdx.x <= GX_ - 2) {
        __half2 macc = __float2half2_rn(0.0f);
        for (int i = tid; i < NV4; i += NT) {
            int ly = i / (TW / 4);
            int lxg = (i - ly * (TW / 4)) * 4;
            int gy = min(max(ty0 + ly, 0), H_ - 1);
            int idx = gy * W_ + tx0 + lxg;
            float4 ax = *(const float4*)(Ax + idx);
            float4 ay = *(const float4*)(Ay + idx);
            float4 bx = *(const float4*)(Bx + idx);
            float4 by = *(const float4*)(By + idx);
            int c = ly * TW + lxg;
            uint4 va = make_uint4(h2u(__floats2half2_rn(ax.x, ay.x)),
                                  h2u(__floats2half2_rn(ax.y, ay.y)),
                                  h2u(__floats2half2_rn(ax.z, ay.z)),
                                  h2u(__floats2half2_rn(ax.w, ay.w)));
            uint4 vb = make_uint4(h2u(__floats2half2_rn(bx.x, by.x)),
                                  h2u(__floats2half2_rn(bx.y, by.y)),
                                  h2u(__floats2half2_rn(bx.z, by.z)),
                                  h2u(__floats2half2_rn(bx.w, by.w)));
            *(uint4*)&tA[c] = va;
            *(uint4*)&tB[c] = vb;
            // Clean check on packed half2 values (fma pipe, conservative thr).
            __half2 m0 = __hmax2(__habs2(u2h(va.x)), __habs2(u2h(va.y)));
            __half2 m1 = __hmax2(__habs2(u2h(va.z)), __habs2(u2h(va.w)));
            __half2 m2 = __hmax2(__habs2(u2h(vb.x)), __habs2(u2h(vb.y)));
            __half2 m3 = __hmax2(__habs2(u2h(vb.z)), __habs2(u2h(vb.w)));
            macc = __hmax2(macc, __hmax2(__hmax2(m0, m1), __hmax2(m2, m3)));
        }
        float hm = fmaxf(__half2float(__low2half(macc)),
                         __half2float(__high2half(macc)));
        if (hm >= CLEAN_TH_H) dirty = 1;
    } else {
        for (int i = tid; i < TSZ; i += NT) {
            int ly = i / TW, lx = i - ly * TW;
            int gx = min(max(tx0 + lx, 0), W_ - 1);
            int gy = min(max(ty0 + ly, 0), H_ - 1);
            int idx = gy * W_ + gx;
            float fax = __ldg(Ax + idx), fay = __ldg(Ay + idx);
            float fbx = __ldg(Bx + idx), fby = __ldg(By + idx);
            if (fmaxf(fmaxf(fabsf(fax), fabsf(fay)),
                      fmaxf(fabsf(fbx), fabsf(fby))) >= CLEAN_TH_F) dirty = 1;
            tA[i] = __floats2half2_rn(fax, fay);
            tB[i] = __floats2half2_rn(fbx, fby);
        }
    }

    bool dataClean = (__syncthreads_or(dirty) == 0);  // also the fill barrier

    int px = blockIdx.x * BX + threadIdx.x;
    int py0 = blockIdx.y * RPB + threadIdx.y;
    bool pxIn = ((unsigned)(px - 14) <= 737u);
    float ub = (float)(threadIdx.x + R_);             // px - tx0

    float s = 0.0f;
    #pragma unroll
    for (int r = 0; r < 4; r++) {
        int py = py0 + r * BY;
        bool fast = dataClean & pxIn & ((unsigned)(py - 14) <= 737u);
        if (fast) {
            int lrow = py - ty0;
            int lown = lrow * TW + (threadIdx.x + R_);
            float2 bo = __half22float2(tB[lown]);
            float2 ao = __half22float2(tA[lown]);
            float vb = (float)lrow;
            s += dir_fast(tA, bo.x, bo.y, ub, vb)
               + dir_fast(tB, ao.x, ao.y, ub, vb);
        } else {
            int idx = py * W_ + px;
            float aox = __ldg(Ax + idx), aoy = __ldg(Ay + idx);
            float box = __ldg(Bx + idx), boy = __ldg(By + idx);
            float Gx = (float)px * INVW;
            float Gy = (float)py * INVH;
            s += dir_diff(tA, Ax, Ay, box, boy, px, py, tx0, ty0, Gx, Gy)
               + dir_diff(tB, Bx, By, aox, aoy, px, py, tx0, ty0, Gx, Gy);
        }
    }

    // Block reduction (16 warps)
    #pragma unroll
    for (int o = 16; o > 0; o >>= 1)
        s += __shfl_down_sync(0xffffffffu, s, o);
    __shared__ float shred[NT / 32];
    if ((tid & 31) == 0) shred[tid >> 5] = s;
    __syncthreads();
    if (tid < 16) {
        float v = shred[tid];
        #pragma unroll
        for (int o = 8; o > 0; o >>= 1)
            v += __shfl_down_sync(0x0000ffffu, v, o);
        if (tid == 0) {
            int bid = blockIdx.x + GX_ * (blockIdx.y + GY_ * blockIdx.z);
            g_partials[bid] = v;
        }
    }

    // Last-block-standing fused final reduce (deterministic).
    __shared__ bool amLast;
    __threadfence();
    if (tid == 0) {
        unsigned long long old = atomicAdd(&g_ticket, 1ULL);
        amLast = ((old % (unsigned long long)NBLK) == (unsigned long long)(NBLK - 1));
    }
    __syncthreads();
    if (amLast) {
        const float4* p4 = (const float4*)g_partials;  // NBLK % 4 == 0
        const int n4 = NBLK / 4;                       // 1152
        double acc = 0.0;
        for (int i = tid; i < n4; i += NT) {
            float4 v = __ldcg(p4 + i);
            acc += (double)((v.x + v.y) + (v.z + v.w));
        }
        #pragma unroll
        for (int o = 16; o > 0; o >>= 1)
            acc += __shfl_down_sync(0xffffffffu, acc, o);
        __shared__ double shd[NT / 32];
        if ((tid & 31) == 0) shd[tid >> 5] = acc;
        __syncthreads();
        if (tid < 16) {
            double v = shd[tid];
            #pragma unroll
            for (int o = 8; o > 0; o >>= 1)
                v += __shfl_down_sync(0x0000ffffu, v, o);
            if (tid == 0)
                out[0] = (float)(v / ((double)N_ * (double)HW_));
        }
    }
}

extern "C" void kernel_launch(void* const* d_in, const int* in_sizes, int n_in,
                              void* d_out, int out_size)
{
    const float* A = (const float*)d_in[0];  // UV_AtoB
    const float* B = (const float*)d_in[1];  // UV_BtoA
    dim3 block(BX, BY);
    dim3 grid(GX_, GY_, N_);
    fused_cycle_kernel<<<grid, block>>>(A, B, (float*)d_out);
}

// round 13
// speedup vs baseline: 2.5164x; 1.0003x over previous
#include <cuda_runtime.h>
#include <cuda_fp16.h>

#define W_ 768
#define H_ 768
#define N_ 16
#define HW_ (H_ * W_)
#define BX 32
#define BY 16
#define NT (BX * BY)           /* 512 */
#define RPB 64                 /* pixel rows per block (4 per thread) */
#define R_ 8
#define TW 52                  /* padded tile width (mult of 4) */
#define TH (RPB + 2 * R_ + 1)  /* 81 */
#define TSZ (TW * TH)          /* 4212 half2 cells */
#define NV4 (TSZ / 4)          /* 1053 */
#define GX_ (W_ / BX)          /* 24 */
#define GY_ (H_ / RPB)         /* 12 */
#define NBLK (GX_ * GY_ * N_)  /* 4608 */
#define EPS2 1.0e-6f
#define INVW (1.0f / 767.0f)
#define INVH (1.0f / 767.0f)
#define WM1F 767.0f
#define HM1F 767.0f
#define CLEAN_TH_H 6.95f
#define CLEAN_TH_F 6.98f

__device__ float g_partials[NBLK];
__device__ unsigned long long g_ticket;  // monotonic across graph replays

typedef unsigned long long u64;

__device__ __forceinline__ u64 packf2(float lo, float hi)
{
    u64 r; asm("mov.b64 %0, {%1, %2};" : "=l"(r) : "f"(lo), "f"(hi)); return r;
}
__device__ __forceinline__ void unpackf2(u64 v, float& lo, float& hi)
{
    asm("mov.b64 {%0, %1}, %2;" : "=f"(lo), "=f"(hi) : "l"(v));
}
#define ADD_F32X2(out, a, b) \
    asm("add.rn.f32x2 %0, %1, %2;" : "=l"(out) : "l"(a), "l"(b))
#define MUL_F32X2(out, a, b) \
    asm("mul.rn.f32x2 %0, %1, %2;" : "=l"(out) : "l"(a), "l"(b))

__device__ __forceinline__ float fast_sqrt(float v)
{
    return v * __frsqrt_rn(v);   // v >= EPS2 > 0 always
}

// General m1 = warp(GridXY, flo1) at integer pixel (ix,iy): closed form.
__device__ __forceinline__ float2 m1_from(float fxv, float fyv, int ix, int iy)
{
    float gx = (float)ix + fxv;
    float gy = (float)iy + fyv;
    float x0f = floorf(gx), y0f = floorf(gy);
    float wx1 = gx - x0f, wy1 = gy - y0f;
    float wx0 = 1.0f - wx1, wy0 = 1.0f - wy1;
    int x0 = (int)x0f, y0 = (int)y0f;
    bool vx0 = ((unsigned)x0 < (unsigned)W_);
    bool vx1 = ((unsigned)(x0 + 1) < (unsigned)W_);
    bool vy0 = ((unsigned)y0 < (unsigned)H_);
    bool vy1 = ((unsigned)(y0 + 1) < (unsigned)H_);
    float c00 = (vx0 && vy0) ? wx0 * wy0 : 0.0f;
    float c10 = (vx1 && vy0) ? wx1 * wy0 : 0.0f;
    float c01 = (vx0 && vy1) ? wx0 * wy1 : 0.0f;
    float c11 = (vx1 && vy1) ? wx1 * wy1 : 0.0f;
    float m = (c00 + c10) + (c01 + c11);
    float cx1 = c10 + c11;
    float cy1 = c01 + c11;
    float ox = fmaf(m, (float)x0, cx1) * INVW;
    float oy = fmaf(m, (float)y0, cy1) * INVH;
    float M = (m < 0.9999f) ? 0.0f : 1.0f;
    return make_float2(ox * M, oy * M);
}

__device__ __forceinline__ float slow_eval(
    float2 f00, float2 f10, float2 f01, float2 f11,
    int x0, int y0, float wx0, float wx1, float wy0, float wy1,
    float Gx, float Gy)
{
    int x1 = x0 + 1, y1 = y0 + 1;
    bool vx0 = ((unsigned)x0 < (unsigned)W_);
    bool vx1 = ((unsigned)x1 < (unsigned)W_);
    bool vy0 = ((unsigned)y0 < (unsigned)H_);
    bool vy1 = ((unsigned)y1 < (unsigned)H_);
    float w00 = (vx0 && vy0) ? wx0 * wy0 : 0.0f;
    float w10 = (vx1 && vy0) ? wx1 * wy0 : 0.0f;
    float w01 = (vx0 && vy1) ? wx0 * wy1 : 0.0f;
    float w11 = (vx1 && vy1) ? wx1 * wy1 : 0.0f;

    float2 v00 = m1_from(f00.x, f00.y, x0, y0);
    float2 v10 = m1_from(f10.x, f10.y, x1, y0);
    float2 v01 = m1_from(f01.x, f01.y, x0, y1);
    float2 v11 = m1_from(f11.x, f11.y, x1, y1);

    float mask = (w00 + w10) + (w01 + w11);
    float mx = fmaf(w00, v00.x, fmaf(w10, v10.x, fmaf(w01, v01.x, w11 * v11.x)));
    float my = fmaf(w00, v00.y, fmaf(w10, v10.y, fmaf(w01, v01.y, w11 * v11.y)));
    float M = (mask < 0.9999f) ? 0.0f : 1.0f;
    mx *= M; my *= M;
    float dx = Gx - mx, dy = Gy - my;
    return fast_sqrt(fmaf(dx, dx, fmaf(dy, dy, EPS2)));
}

// General per-pixel path (margin/dirty pixels).
__device__ __forceinline__ float dir_diff(const __half2* __restrict__ t1,
                                          const float* __restrict__ g1x,
                                          const float* __restrict__ g1y,
                                          float f2x, float f2y,
                                          int px, int py, int tx0, int ty0,
                                          float Gx, float Gy)
{
    float sxf = (float)px + f2x;
    float syf = (float)py + f2y;
    float x0f = floorf(sxf), y0f = floorf(syf);
    float wx1 = sxf - x0f, wy1 = syf - y0f;
    float wx0 = 1.0f - wx1, wy0 = 1.0f - wy1;
    int x0 = (int)x0f, y0 = (int)y0f;

    int lx0 = x0 - tx0, ly0 = y0 - ty0;
    if (((unsigned)lx0 <= (unsigned)(TW - 2)) &
        ((unsigned)ly0 <= (unsigned)(TH - 2))) {
        int b = ly0 * TW + lx0;
        float2 f00 = __half22float2(t1[b]);
        float2 f10 = __half22float2(t1[b + 1]);
        float2 f01 = __half22float2(t1[b + TW]);
        float2 f11 = __half22float2(t1[b + TW + 1]);

        float x1f = x0f + 1.0f, y1f = y0f + 1.0f;
        float mnfx = fminf(fminf(f00.x, f01.x), fminf(f10.x, f11.x));
        float mxfx = fmaxf(fmaxf(f00.x, f01.x), fmaxf(f10.x, f11.x));
        float mnfy = fminf(fminf(f00.y, f01.y), fminf(f10.y, f11.y));
        float mxfy = fmaxf(fmaxf(f00.y, f01.y), fmaxf(f10.y, f11.y));
        bool inner = (sxf >= 0.0f) & (sxf <= WM1F) &
                     (syf >= 0.0f) & (syf <= HM1F) &
                     (x0f + mnfx >= 0.0f) & (x1f + mxfx <= WM1F) &
                     (y0f + mnfy >= 0.0f) & (y1f + mxfy <= HM1F);
        if (inner) {
            float ftx = fmaf(wx1, f10.x - f00.x, f00.x);
            float fbx = fmaf(wx1, f11.x - f01.x, f01.x);
            float bfx = fmaf(wy1, fbx - ftx, ftx);
            float fty = fmaf(wx1, f10.y - f00.y, f00.y);
            float fby = fmaf(wx1, f11.y - f01.y, f01.y);
            float bfy = fmaf(wy1, fby - fty, fty);
            float dx = (f2x + bfx) * INVW;
            float dy = (f2y + bfy) * INVH;
            return fast_sqrt(fmaf(dx, dx, fmaf(dy, dy, EPS2)));
        }
        return slow_eval(f00, f10, f01, f11, x0, y0, wx0, wx1, wy0, wy1, Gx, Gy);
    }
    {
        int x1 = x0 + 1, y1 = y0 + 1;
        int xc0 = min(max(x0, 0), W_ - 1);
        int xc1 = min(max(x1, 0), W_ - 1);
        int yc0 = min(max(y0, 0), H_ - 1);
        int yc1 = min(max(y1, 0), H_ - 1);
        int b00 = yc0 * W_ + xc0, b10 = yc0 * W_ + xc1;
        int b01 = yc1 * W_ + xc0, b11 = yc1 * W_ + xc1;
        float2 f00 = make_float2(__ldg(g1x + b00), __ldg(g1y + b00));
        float2 f10 = make_float2(__ldg(g1x + b10), __ldg(g1y + b10));
        float2 f01 = make_float2(__ldg(g1x + b01), __ldg(g1y + b01));
        float2 f11 = make_float2(__ldg(g1x + b11), __ldg(g1y + b11));
        return slow_eval(f00, f10, f01, f11, x0, y0, wx0, wx1, wy0, wy1, Gx, Gy);
    }
}

// Per-pixel fast path for the general (mixed) loop.
__device__ __forceinline__ float dir_fast(const __half2* __restrict__ t1,
                                          float f2x, float f2y,
                                          float ub, float vb)
{
    float u = ub + f2x;
    float v = vb + f2y;
    int iu = (int)u;                     // trunc == floor (u > 0)
    int iv = (int)v;
    float wx1 = u - (float)iu;
    float wy1 = v - (float)iv;
    int b = iv * TW + iu;

    __half2 f00 = t1[b];
    __half2 f10 = t1[b + 1];
    __half2 f01 = t1[b + TW];
    __half2 f11 = t1[b + TW + 1];

    __half2 hx1 = __float2half2_rn(wx1);
    __half2 hy1 = __float2half2_rn(wy1);

    __half2 top = __hfma2(__hsub2(f10, f00), hx1, f00);
    __half2 bot = __hfma2(__hsub2(f11, f01), hx1, f01);
    __half2 r   = __hfma2(__hsub2(bot, top), hy1, top);
    float2 bf = __half22float2(r);

    float dx = (f2x + bf.x) * INVW;
    float dy = (f2y + bf.y) * INVH;
    return fast_sqrt(fmaf(dx, dx, fmaf(dy, dy, EPS2)));
}

// Uniform-block fast path: packed f32x2 for (u,v) and the output tail.
__device__ __forceinline__ float dir_fast_u(const __half2* __restrict__ t1,
                                            u64 f2p, u64 uvb, u64 invp)
{
    u64 uvp; ADD_F32X2(uvp, uvb, f2p);
    float u, v; unpackf2(uvp, u, v);
    int iu = (int)u;                     // u,v > 0: trunc == floor
    int iv = (int)v;
    float wx1 = u - (float)iu;
    float wy1 = v - (float)iv;
    int b = iv * TW + iu;

    __half2 f00 = t1[b];
    __half2 f10 = t1[b + 1];
    __half2 f01 = t1[b + TW];
    __half2 f11 = t1[b + TW + 1];

    __half2 hx1 = __float2half2_rn(wx1);
    __half2 hy1 = __float2half2_rn(wy1);

    __half2 top = __hfma2(__hsub2(f10, f00), hx1, f00);
    __half2 bot = __hfma2(__hsub2(f11, f01), hx1, f01);
    __half2 r   = __hfma2(__hsub2(bot, top), hy1, top);
    float2 bf = __half22float2(r);

    u64 dp; ADD_F32X2(dp, f2p, packf2(bf.x, bf.y));
    MUL_F32X2(dp, dp, invp);
    float dx, dy; unpackf2(dp, dx, dy);
    return fast_sqrt(fmaf(dx, dx, fmaf(dy, dy, EPS2)));
}

__device__ __forceinline__ unsigned h2u(__half2 h)
{
    return *reinterpret_cast<unsigned*>(&h);
}
__device__ __forceinline__ __half2 u2h(unsigned u)
{
    return *reinterpret_cast<__half2*>(&u);
}

__global__ __launch_bounds__(NT, 4)
void fused_cycle_kernel(const float* __restrict__ A, const float* __restrict__ B,
                        float* __restrict__ out)
{
    __shared__ __half2 tA[TSZ];
    __shared__ __half2 tB[TSZ];

    int n = blockIdx.z;
    const float* Ax = A + (size_t)n * 2 * HW_;
    const float* Ay = Ax + HW_;
    const float* Bx = B + (size_t)n * 2 * HW_;
    const float* By = Bx + HW_;

    int tx0 = blockIdx.x * BX - R_;
    int ty0 = blockIdx.y * RPB - R_;
    int tid = threadIdx.y * BX + threadIdx.x;

    int dirty = 0;

    // Tile fill: tile cell == clamped-global value, quantized to half2.
    if (blockIdx.x >= 1 && blockIdx.x <= GX_ - 2) {
        __half2 macc = __float2half2_rn(0.0f);
        for (int i = tid; i < NV4; i += NT) {
            int ly = i / (TW / 4);
            int lxg = (i - ly * (TW / 4)) * 4;
            int gy = min(max(ty0 + ly, 0), H_ - 1);
            int idx = gy * W_ + tx0 + lxg;
            float4 ax = *(const float4*)(Ax + idx);
            float4 ay = *(const float4*)(Ay + idx);
            float4 bx = *(const float4*)(Bx + idx);
            float4 by = *(const float4*)(By + idx);
            int c = ly * TW + lxg;
            uint4 va = make_uint4(h2u(__floats2half2_rn(ax.x, ay.x)),
                                  h2u(__floats2half2_rn(ax.y, ay.y)),
                                  h2u(__floats2half2_rn(ax.z, ay.z)),
                                  h2u(__floats2half2_rn(ax.w, ay.w)));
            uint4 vb = make_uint4(h2u(__floats2half2_rn(bx.x, by.x)),
                                  h2u(__floats2half2_rn(bx.y, by.y)),
                                  h2u(__floats2half2_rn(bx.z, by.z)),
                                  h2u(__floats2half2_rn(bx.w, by.w)));
            *(uint4*)&tA[c] = va;
            *(uint4*)&tB[c] = vb;
            __half2 m0 = __hmax2(__habs2(u2h(va.x)), __habs2(u2h(va.y)));
            __half2 m1 = __hmax2(__habs2(u2h(va.z)), __habs2(u2h(va.w)));
            __half2 m2 = __hmax2(__habs2(u2h(vb.x)), __habs2(u2h(vb.y)));
            __half2 m3 = __hmax2(__habs2(u2h(vb.z)), __habs2(u2h(vb.w)));
            macc = __hmax2(macc, __hmax2(__hmax2(m0, m1), __hmax2(m2, m3)));
        }
        float hm = fmaxf(__half2float(__low2half(macc)),
                         __half2float(__high2half(macc)));
        if (hm >= CLEAN_TH_H) dirty = 1;
    } else {
        for (int i = tid; i < TSZ; i += NT) {
            int ly = i / TW, lx = i - ly * TW;
            int gx = min(max(tx0 + lx, 0), W_ - 1);
            int gy = min(max(ty0 + ly, 0), H_ - 1);
            int idx = gy * W_ + gx;
            float fax = __ldg(Ax + idx), fay = __ldg(Ay + idx);
            float fbx = __ldg(Bx + idx), fby = __ldg(By + idx);
            if (fmaxf(fmaxf(fabsf(fax), fabsf(fay)),
                      fmaxf(fabsf(fbx), fabsf(fby))) >= CLEAN_TH_F) dirty = 1;
            tA[i] = __floats2half2_rn(fax, fay);
            tB[i] = __floats2half2_rn(fbx, fby);
        }
    }

    bool dataClean = (__syncthreads_or(dirty) == 0);  // also the fill barrier

    // Blocks fully inside the margin: all pixels provably interior.
    bool blockInterior = (blockIdx.x >= 1) & (blockIdx.x <= GX_ - 2) &
                         (blockIdx.y >= 1) & (blockIdx.y <= GY_ - 2);

    float s = 0.0f;
    if (blockInterior & dataClean) {
        // Uniform fast loop: no per-row predicates, no slow path.
        const u64 invp = packf2(INVW, INVH);
        float ub = (float)(threadIdx.x + R_);
        int lown = (threadIdx.y + R_) * TW + (threadIdx.x + R_);
        float vb = (float)(threadIdx.y + R_);
        #pragma unroll
        for (int r = 0; r < 4; r++) {
            float2 bo = __half22float2(tB[lown]);
            float2 ao = __half22float2(tA[lown]);
            u64 uvb = packf2(ub, vb);
            s += dir_fast_u(tA, packf2(bo.x, bo.y), uvb, invp)
               + dir_fast_u(tB, packf2(ao.x, ao.y), uvb, invp);
            lown += BY * TW;
            vb += (float)BY;
        }
    } else {
        int px = blockIdx.x * BX + threadIdx.x;
        int py0 = blockIdx.y * RPB + threadIdx.y;
        bool pxIn = ((unsigned)(px - 14) <= 737u);
        float ub = (float)(threadIdx.x + R_);
        #pragma unroll
        for (int r = 0; r < 4; r++) {
            int py = py0 + r * BY;
            bool fast = dataClean & pxIn & ((unsigned)(py - 14) <= 737u);
            if (fast) {
                int lrow = py - ty0;
                int lown = lrow * TW + (threadIdx.x + R_);
                float2 bo = __half22float2(tB[lown]);
                float2 ao = __half22float2(tA[lown]);
                float vb = (float)lrow;
                s += dir_fast(tA, bo.x, bo.y, ub, vb)
                   + dir_fast(tB, ao.x, ao.y, ub, vb);
            } else {
                int idx = py * W_ + px;
                float aox = __ldg(Ax + idx), aoy = __ldg(Ay + idx);
                float box = __ldg(Bx + idx), boy = __ldg(By + idx);
                float Gx = (float)px * INVW;
                float Gy = (float)py * INVH;
                s += dir_diff(tA, Ax, Ay, box, boy, px, py, tx0, ty0, Gx, Gy)
                   + dir_diff(tB, Bx, By, aox, aoy, px, py, tx0, ty0, Gx, Gy);
            }
        }
    }

    // Block reduction (16 warps)
    #pragma unroll
    for (int o = 16; o > 0; o >>= 1)
        s += __shfl_down_sync(0xffffffffu, s, o);
    __shared__ float shred[NT / 32];
    if ((tid & 31) == 0) shred[tid >> 5] = s;
    __syncthreads();
    if (tid < 16) {
        float v = shred[tid];
        #pragma unroll
        for (int o = 8; o > 0; o >>= 1)
            v += __shfl_down_sync(0x0000ffffu, v, o);
        if (tid == 0) {
            int bid = blockIdx.x + GX_ * (blockIdx.y + GY_ * blockIdx.z);
            g_partials[bid] = v;
        }
    }

    // Last-block-standing fused final reduce (deterministic).
    __shared__ bool amLast;
    __threadfence();
    if (tid == 0) {
        unsigned long long old = atomicAdd(&g_ticket, 1ULL);
        amLast = ((old % (unsigned long long)NBLK) == (unsigned long long)(NBLK - 1));
    }
    __syncthreads();
    if (amLast) {
        const float4* p4 = (const float4*)g_partials;  // NBLK % 4 == 0
        const int n4 = NBLK / 4;                       // 1152
        double acc = 0.0;
        for (int i = tid; i < n4; i += NT) {
            float4 v = __ldcg(p4 + i);
            acc += (double)((v.x + v.y) + (v.z + v.w));
        }
        #pragma unroll
        for (int o = 16; o > 0; o >>= 1)
            acc += __shfl_down_sync(0xffffffffu, acc, o);
        __shared__ double shd[NT / 32];
        if ((tid & 31) == 0) shd[tid >> 5] = acc;
        __syncthreads();
        if (tid < 16) {
            double v = shd[tid];
            #pragma unroll
            for (int o = 8; o > 0; o >>= 1)
                v += __shfl_down_sync(0x0000ffffu, v, o);
            if (tid == 0)
                out[0] = (float)(v / ((double)N_ * (double)HW_));
        }
    }
}

extern "C" void kernel_launch(void* const* d_in, const int* in_sizes, int n_in,
                              void* d_out, int out_size)
{
    const float* A = (const float*)d_in[0];  // UV_AtoB
    const float* B = (const float*)d_in[1];  // UV_BtoA
    dim3 block(BX, BY);
    dim3 grid(GX_, GY_, N_);
    fused_cycle_kernel<<<grid, block>>>(A, B, (float*)d_out);
}